// round 1
// baseline (speedup 1.0000x reference)
#include <cuda_runtime.h>
#include <cuda_bf16.h>
#include <math.h>

// Problem shape (fixed for this problem instance)
#define NTOK 2048      // B*T
#define HDIM 1024      // H
#define FDIM 4096      // F
#define NEXP 8         // E
#define TOPK 2
#define NOISE_SCALE 0.01f

// GEMM tiling
#define BM 128
#define BN 64
#define BK 16

// ---------------- device scratch (allocation-free: __device__ globals) ------
__device__ int   g_sel[NTOK * TOPK];
__device__ float g_wt [NTOK * TOPK];
__device__ int   g_cnt[NEXP];
__device__ int   g_list[NEXP * NTOK];
__device__ float g_lw  [NEXP * NTOK];
// act = silu(x@W1+b1) * (x@W3+b3), per (expert, local-row): 8*2048*4096 f32 = 256MB
__device__ float g_act[(size_t)NEXP * NTOK * FDIM];

__device__ __forceinline__ float siluf(float v) {
    return v / (1.0f + expf(-v));
}

// ---------------- router: logits, softmax top-2, weights --------------------
__global__ void router_kernel(const float* __restrict__ x,
                              const float* __restrict__ noise,
                              const float* __restrict__ Wg,
                              const float* __restrict__ bg,
                              float* out_logits,   // may be null
                              float* out_sel) {    // may be null
    int n = blockIdx.x;
    int tid = threadIdx.x;          // 128 threads
    const float* xr = x + (size_t)n * HDIM;

    float acc[NEXP];
#pragma unroll
    for (int e = 0; e < NEXP; e++) acc[e] = 0.0f;

    for (int h = tid; h < HDIM; h += 128) {
        float xv = xr[h];
        const float* wr = Wg + (size_t)h * NEXP;
#pragma unroll
        for (int e = 0; e < NEXP; e++) acc[e] += xv * wr[e];
    }

    __shared__ float red[NEXP][128];
#pragma unroll
    for (int e = 0; e < NEXP; e++) red[e][tid] = acc[e];
    __syncthreads();
    for (int s = 64; s > 0; s >>= 1) {
        if (tid < s) {
#pragma unroll
            for (int e = 0; e < NEXP; e++) red[e][tid] += red[e][tid + s];
        }
        __syncthreads();
    }

    if (tid == 0) {
        float l[NEXP];
#pragma unroll
        for (int e = 0; e < NEXP; e++)
            l[e] = red[e][0] + bg[e] + NOISE_SCALE * noise[(size_t)n * NEXP + e];

        if (out_logits) {
#pragma unroll
            for (int e = 0; e < NEXP; e++)
                out_logits[(size_t)n * NEXP + e] = l[e];
        }

        // top-2 on logits (softmax is monotone; strict > keeps earliest index, matching lax.top_k)
        int i0 = 0;
#pragma unroll
        for (int e = 1; e < NEXP; e++) if (l[e] > l[i0]) i0 = e;
        int i1 = (i0 == 0) ? 1 : 0;
#pragma unroll
        for (int e = 0; e < NEXP; e++) {
            if (e != i0 && l[e] > l[i1]) i1 = e;
        }

        float r = expf(l[i1] - l[i0]);     // <= 1
        float w0 = 1.0f / (1.0f + r);
        float w1 = r / (1.0f + r);

        g_sel[n * TOPK + 0] = i0;
        g_sel[n * TOPK + 1] = i1;
        g_wt [n * TOPK + 0] = w0;
        g_wt [n * TOPK + 1] = w1;

        if (out_sel) {
            out_sel[n * TOPK + 0] = (float)i0;
            out_sel[n * TOPK + 1] = (float)i1;
        }
    }
}

// ---------------- stable per-expert compaction -------------------------------
__global__ void build_lists_kernel() {
    int e = blockIdx.x;       // one block (one warp) per expert
    int lane = threadIdx.x;   // 32 threads
    int c = 0;
    for (int n0 = 0; n0 < NTOK; n0 += 32) {
        int n = n0 + lane;
        int s0 = g_sel[n * TOPK + 0];
        int s1 = g_sel[n * TOPK + 1];
        bool m0 = (s0 == e);
        bool m1 = (s1 == e);
        bool any = m0 || m1;           // can't be both (top-2 indices distinct)
        unsigned mask = __ballot_sync(0xffffffffu, any);
        if (any) {
            int pos = c + __popc(mask & ((1u << lane) - 1u));
            g_list[e * NTOK + pos] = n;
            g_lw  [e * NTOK + pos] = m0 ? g_wt[n * TOPK + 0] : g_wt[n * TOPK + 1];
        }
        c += __popc(mask);
    }
    if (lane == 0) g_cnt[e] = c;
}

// ---------------- GEMM1: act = silu(Xg@W1 + b1) * (Xg@W3 + b3) ---------------
// grid: (FDIM/BN, NTOK/BM, NEXP), 256 threads
__global__ __launch_bounds__(256)
void gemm1_kernel(const float* __restrict__ x,
                  const float* __restrict__ W1, const float* __restrict__ b1,
                  const float* __restrict__ W3, const float* __restrict__ b3) {
    int e   = blockIdx.z;
    int cnt = g_cnt[e];
    int m0  = blockIdx.y * BM;
    if (m0 >= cnt) return;
    int n0  = blockIdx.x * BN;

    __shared__ float As [BK][BM + 4];   // 132 cols: keeps 16B alignment of 8-f segments
    __shared__ float B1s[BK][BN];
    __shared__ float B3s[BK][BN];
    __shared__ int   toks[BM];

    int tid = threadIdx.x;
    int tx = tid & 15;        // n-group
    int ty = tid >> 4;        // m-group

    if (tid < BM) {
        int r = m0 + tid;
        toks[tid] = (r < cnt) ? g_list[e * NTOK + r] : -1;
    }
    __syncthreads();

    int rowA  = tid >> 1;        // 0..127
    int halfA = tid & 1;         // 0/1 -> 8 floats each
    int tokA  = toks[rowA];
    int kB = tid >> 4;           // 0..15
    int nB = (tid & 15) << 2;    // 0..60

    const float* W1e = W1 + (size_t)e * HDIM * FDIM;
    const float* W3e = W3 + (size_t)e * HDIM * FDIM;

    float acc1[8][4];
    float acc3[8][4];
#pragma unroll
    for (int i = 0; i < 8; i++)
#pragma unroll
        for (int j = 0; j < 4; j++) { acc1[i][j] = 0.0f; acc3[i][j] = 0.0f; }

    for (int kk = 0; kk < HDIM; kk += BK) {
        float4 a0 = make_float4(0.f, 0.f, 0.f, 0.f);
        float4 a1 = make_float4(0.f, 0.f, 0.f, 0.f);
        if (tokA >= 0) {
            const float* xp = x + (size_t)tokA * HDIM + kk + (halfA << 3);
            a0 = *(const float4*)(xp);
            a1 = *(const float4*)(xp + 4);
        }
        float4 b1r = *(const float4*)(W1e + (size_t)(kk + kB) * FDIM + n0 + nB);
        float4 b3r = *(const float4*)(W3e + (size_t)(kk + kB) * FDIM + n0 + nB);

        __syncthreads();   // previous compute done before overwriting smem
        int kA = halfA << 3;
        As[kA + 0][rowA] = a0.x; As[kA + 1][rowA] = a0.y;
        As[kA + 2][rowA] = a0.z; As[kA + 3][rowA] = a0.w;
        As[kA + 4][rowA] = a1.x; As[kA + 5][rowA] = a1.y;
        As[kA + 6][rowA] = a1.z; As[kA + 7][rowA] = a1.w;
        *(float4*)&B1s[kB][nB] = b1r;
        *(float4*)&B3s[kB][nB] = b3r;
        __syncthreads();

#pragma unroll
        for (int k = 0; k < BK; k++) {
            float4 av0 = *(const float4*)&As[k][ty * 8];
            float4 av1 = *(const float4*)&As[k][ty * 8 + 4];
            float4 bb1 = *(const float4*)&B1s[k][tx << 2];
            float4 bb3 = *(const float4*)&B3s[k][tx << 2];
            float a[8] = {av0.x, av0.y, av0.z, av0.w, av1.x, av1.y, av1.z, av1.w};
            float p1[4] = {bb1.x, bb1.y, bb1.z, bb1.w};
            float p3[4] = {bb3.x, bb3.y, bb3.z, bb3.w};
#pragma unroll
            for (int i = 0; i < 8; i++) {
#pragma unroll
                for (int j = 0; j < 4; j++) {
                    acc1[i][j] += a[i] * p1[j];
                    acc3[i][j] += a[i] * p3[j];
                }
            }
        }
    }

    float4 b1v = *(const float4*)(b1 + (size_t)e * FDIM + n0 + (tx << 2));
    float4 b3v = *(const float4*)(b3 + (size_t)e * FDIM + n0 + (tx << 2));
    float bias1[4] = {b1v.x, b1v.y, b1v.z, b1v.w};
    float bias3[4] = {b3v.x, b3v.y, b3v.z, b3v.w};

#pragma unroll
    for (int i = 0; i < 8; i++) {
        int r = m0 + ty * 8 + i;
        if (r >= cnt) continue;
        float4 o;
        float c1, c3;
        c1 = acc1[i][0] + bias1[0]; c3 = acc3[i][0] + bias3[0]; o.x = siluf(c1) * c3;
        c1 = acc1[i][1] + bias1[1]; c3 = acc3[i][1] + bias3[1]; o.y = siluf(c1) * c3;
        c1 = acc1[i][2] + bias1[2]; c3 = acc3[i][2] + bias3[2]; o.z = siluf(c1) * c3;
        c1 = acc1[i][3] + bias1[3]; c3 = acc3[i][3] + bias3[3]; o.w = siluf(c1) * c3;
        *(float4*)(g_act + ((size_t)e * NTOK + r) * FDIM + n0 + (tx << 2)) = o;
    }
}

// ---------------- GEMM2: out[tok] += w * (act@W2 + b2) -----------------------
// grid: (HDIM/BN, NTOK/BM, NEXP), 256 threads
__global__ __launch_bounds__(256)
void gemm2_kernel(const float* __restrict__ W2, const float* __restrict__ b2,
                  float* __restrict__ out) {
    int e   = blockIdx.z;
    int cnt = g_cnt[e];
    int m0  = blockIdx.y * BM;
    if (m0 >= cnt) return;
    int n0  = blockIdx.x * BN;

    __shared__ float As[BK][BM + 4];
    __shared__ float Bs[BK][BN];
    __shared__ int   toks[BM];
    __shared__ float ws[BM];

    int tid = threadIdx.x;
    int tx = tid & 15;
    int ty = tid >> 4;

    if (tid < BM) {
        int r = m0 + tid;
        toks[tid] = (r < cnt) ? g_list[e * NTOK + r] : -1;
        ws[tid]   = (r < cnt) ? g_lw  [e * NTOK + r] : 0.0f;
    }
    __syncthreads();

    int rowA  = tid >> 1;
    int halfA = tid & 1;
    int rA    = m0 + rowA;
    bool validA = (rA < cnt);
    const float* Ae  = g_act + (size_t)e * NTOK * FDIM;
    const float* W2e = W2 + (size_t)e * FDIM * HDIM;
    int kB = tid >> 4;
    int nB = (tid & 15) << 2;

    float acc[8][4];
#pragma unroll
    for (int i = 0; i < 8; i++)
#pragma unroll
        for (int j = 0; j < 4; j++) acc[i][j] = 0.0f;

    for (int kk = 0; kk < FDIM; kk += BK) {
        float4 a0 = make_float4(0.f, 0.f, 0.f, 0.f);
        float4 a1 = make_float4(0.f, 0.f, 0.f, 0.f);
        if (validA) {
            const float* ap = Ae + (size_t)rA * FDIM + kk + (halfA << 3);
            a0 = *(const float4*)(ap);
            a1 = *(const float4*)(ap + 4);
        }
        float4 br = *(const float4*)(W2e + (size_t)(kk + kB) * HDIM + n0 + nB);

        __syncthreads();
        int kA = halfA << 3;
        As[kA + 0][rowA] = a0.x; As[kA + 1][rowA] = a0.y;
        As[kA + 2][rowA] = a0.z; As[kA + 3][rowA] = a0.w;
        As[kA + 4][rowA] = a1.x; As[kA + 5][rowA] = a1.y;
        As[kA + 6][rowA] = a1.z; As[kA + 7][rowA] = a1.w;
        *(float4*)&Bs[kB][nB] = br;
        __syncthreads();

#pragma unroll
        for (int k = 0; k < BK; k++) {
            float4 av0 = *(const float4*)&As[k][ty * 8];
            float4 av1 = *(const float4*)&As[k][ty * 8 + 4];
            float4 bbv = *(const float4*)&Bs[k][tx << 2];
            float a[8] = {av0.x, av0.y, av0.z, av0.w, av1.x, av1.y, av1.z, av1.w};
            float b[4] = {bbv.x, bbv.y, bbv.z, bbv.w};
#pragma unroll
            for (int i = 0; i < 8; i++)
#pragma unroll
                for (int j = 0; j < 4; j++)
                    acc[i][j] += a[i] * b[j];
        }
    }

    float4 b2v = *(const float4*)(b2 + (size_t)e * HDIM + n0 + (tx << 2));
    float bias[4] = {b2v.x, b2v.y, b2v.z, b2v.w};

#pragma unroll
    for (int i = 0; i < 8; i++) {
        int lr = ty * 8 + i;
        int r = m0 + lr;
        if (r >= cnt) continue;
        int tok = toks[lr];
        float w = ws[lr];
        float* op = out + (size_t)tok * HDIM + n0 + (tx << 2);
#pragma unroll
        for (int j = 0; j < 4; j++) {
            float y = acc[i][j] + bias[j];
            atomicAdd(op + j, w * y);   // exactly 2 contributions/token: commutative -> deterministic
        }
    }
}

// ---------------- launch -----------------------------------------------------
extern "C" void kernel_launch(void* const* d_in, const int* in_sizes, int n_in,
                              void* d_out, int out_size) {
    const float* x     = (const float*)d_in[0];
    const float* noise = (const float*)d_in[1];
    const float* Wg    = (const float*)d_in[2];
    const float* bg    = (const float*)d_in[3];
    const float* W1    = (const float*)d_in[4];
    const float* b1    = (const float*)d_in[5];
    const float* W2    = (const float*)d_in[6];
    const float* b2    = (const float*)d_in[7];
    const float* W3    = (const float*)d_in[8];
    const float* b3    = (const float*)d_in[9];

    float* out = (float*)d_out;
    const size_t HID = (size_t)NTOK * HDIM;           // 2,097,152
    const size_t LOG = (size_t)NTOK * NEXP;           // 16,384
    const size_t SEL = (size_t)NTOK * TOPK;           // 4,096

    float* out_logits = nullptr;
    float* out_sel    = nullptr;
    if ((size_t)out_size >= HID + LOG)       out_logits = out + HID;
    if ((size_t)out_size >= HID + LOG + SEL) out_sel    = out + HID + LOG;

    // zero the final_hidden region (accumulated via atomics)
    cudaMemsetAsync(out, 0, HID * sizeof(float));

    router_kernel<<<NTOK, 128>>>(x, noise, Wg, bg, out_logits, out_sel);
    build_lists_kernel<<<NEXP, 32>>>();

    dim3 g1(FDIM / BN, NTOK / BM, NEXP);   // (64, 16, 8)
    gemm1_kernel<<<g1, 256>>>(x, W1, b1, W3, b3);

    dim3 g2(HDIM / BN, NTOK / BM, NEXP);   // (16, 16, 8)
    gemm2_kernel<<<g2, 256>>>(W2, b2, out);
}

// round 3
// speedup vs baseline: 1.9418x; 1.9418x over previous
#include <cuda_runtime.h>
#include <cuda_bf16.h>
#include <math.h>

// Problem shape (fixed)
#define NTOK 2048      // B*T
#define HDIM 1024      // H
#define FDIM 4096      // F
#define NEXP 8         // E
#define TOPK 2
#define NOISE_SCALE 0.01f

// GEMM tiling
#define BM 128
#define BN 64
#define BK 32
#define AS_STR 40              // BK + 8 pad (bf16 elems); 20 words/row
#define ATILE (BM * AS_STR)    // 5120 elems
#define BTILE (BN * AS_STR)    // 2560 elems

// ---------------- device scratch (allocation-free) ---------------------------
__device__ int   g_sel[NTOK * TOPK];
__device__ float g_wt [NTOK * TOPK];
__device__ int   g_cnt[NEXP];
__device__ int   g_list[NEXP * NTOK];
__device__ float g_lw  [NEXP * NTOK];

// split-bf16 (hi/lo) weights, transposed to [E][N][K]
__device__ __align__(16) __nv_bfloat16 g_w1t_h[(size_t)NEXP * FDIM * HDIM];
__device__ __align__(16) __nv_bfloat16 g_w1t_l[(size_t)NEXP * FDIM * HDIM];
__device__ __align__(16) __nv_bfloat16 g_w3t_h[(size_t)NEXP * FDIM * HDIM];
__device__ __align__(16) __nv_bfloat16 g_w3t_l[(size_t)NEXP * FDIM * HDIM];
__device__ __align__(16) __nv_bfloat16 g_w2t_h[(size_t)NEXP * HDIM * FDIM];
__device__ __align__(16) __nv_bfloat16 g_w2t_l[(size_t)NEXP * HDIM * FDIM];
__device__ __align__(16) __nv_bfloat16 g_xh_h [(size_t)NTOK * HDIM];
__device__ __align__(16) __nv_bfloat16 g_xh_l [(size_t)NTOK * HDIM];
__device__ __align__(16) __nv_bfloat16 g_act_h[(size_t)NEXP * NTOK * FDIM];
__device__ __align__(16) __nv_bfloat16 g_act_l[(size_t)NEXP * NTOK * FDIM];

__device__ __forceinline__ float siluf(float v) { return v / (1.0f + expf(-v)); }

__device__ __forceinline__ unsigned pack2(float a, float b) {
    __nv_bfloat162 h = __floats2bfloat162_rn(a, b);
    return *reinterpret_cast<unsigned*>(&h);
}

#define MMA_BF16(d, a0,a1,a2,a3, b0,b1)                                          \
    asm volatile("mma.sync.aligned.m16n8k16.row.col.f32.bf16.bf16.f32 "          \
                 "{%0,%1,%2,%3},{%4,%5,%6,%7},{%8,%9},{%0,%1,%2,%3};\n"          \
                 : "+f"(d[0]), "+f"(d[1]), "+f"(d[2]), "+f"(d[3])                \
                 : "r"(a0), "r"(a1), "r"(a2), "r"(a3), "r"(b0), "r"(b1))

__device__ __forceinline__ void cpa16(unsigned dst, const void* src) {
    asm volatile("cp.async.ca.shared.global [%0], [%1], 16;\n" :: "r"(dst), "l"(src));
}
#define CP_COMMIT() asm volatile("cp.async.commit_group;\n")
#define CP_WAIT0()  asm volatile("cp.async.wait_group 0;\n")
#define CP_WAIT1()  asm volatile("cp.async.wait_group 1;\n")

// ---------------- conversion: x fp32 -> hi/lo bf16 ---------------------------
__global__ void convert_x_kernel(const float* __restrict__ x) {
    int i = blockIdx.x * blockDim.x + threadIdx.x;   // one float4 per thread
    float4 v = reinterpret_cast<const float4*>(x)[i];
    __nv_bfloat16 hx = __float2bfloat16(v.x), hy = __float2bfloat16(v.y);
    __nv_bfloat16 hz = __float2bfloat16(v.z), hw = __float2bfloat16(v.w);
    uint2 oh, ol;
    oh.x = pack2(__bfloat162float(hx), __bfloat162float(hy));
    oh.y = pack2(__bfloat162float(hz), __bfloat162float(hw));
    // repack via floats to keep exact hi
    __nv_bfloat162 h0 = __floats2bfloat162_rn(v.x, v.y);   // same rounding as above
    __nv_bfloat162 h1 = __floats2bfloat162_rn(v.z, v.w);
    oh.x = *reinterpret_cast<unsigned*>(&h0);
    oh.y = *reinterpret_cast<unsigned*>(&h1);
    ol.x = pack2(v.x - __bfloat162float(h0.x), v.y - __bfloat162float(h0.y));
    ol.y = pack2(v.z - __bfloat162float(h1.x), v.w - __bfloat162float(h1.y));
    reinterpret_cast<uint2*>(g_xh_h)[i] = oh;
    reinterpret_cast<uint2*>(g_xh_l)[i] = ol;
}

// ---------------- transpose+convert: W[e][K][N] f32 -> hi/lo [e][N][K] -------
__global__ void transpose_convert_kernel(const float* __restrict__ W,
                                         __nv_bfloat16* __restrict__ Wth,
                                         __nv_bfloat16* __restrict__ Wtl,
                                         int K, int N) {
    __shared__ float tile[32][33];
    int e = blockIdx.z;
    const float* We = W + (size_t)e * K * N;
    int n0 = blockIdx.x * 32, k0 = blockIdx.y * 32;
    int tx = threadIdx.x, ty = threadIdx.y;   // 32 x 8
#pragma unroll
    for (int j = 0; j < 32; j += 8)
        tile[ty + j][tx] = We[(size_t)(k0 + ty + j) * N + n0 + tx];
    __syncthreads();
    size_t base = (size_t)e * K * N;
#pragma unroll
    for (int j = 0; j < 32; j += 8) {
        float v = tile[tx][ty + j];
        __nv_bfloat16 h = __float2bfloat16(v);
        __nv_bfloat16 l = __float2bfloat16(v - __bfloat162float(h));
        size_t idx = base + (size_t)(n0 + ty + j) * K + k0 + tx;
        Wth[idx] = h;
        Wtl[idx] = l;
    }
}

// ---------------- router -----------------------------------------------------
__global__ void router_kernel(const float* __restrict__ x,
                              const float* __restrict__ noise,
                              const float* __restrict__ Wg,
                              const float* __restrict__ bg,
                              float* out_logits, float* out_sel) {
    int n = blockIdx.x;
    int tid = threadIdx.x;          // 128
    const float* xr = x + (size_t)n * HDIM;

    float acc[NEXP];
#pragma unroll
    for (int e = 0; e < NEXP; e++) acc[e] = 0.0f;
    for (int h = tid; h < HDIM; h += 128) {
        float xv = xr[h];
        const float* wr = Wg + (size_t)h * NEXP;
#pragma unroll
        for (int e = 0; e < NEXP; e++) acc[e] += xv * wr[e];
    }

    __shared__ float red[NEXP][128];
#pragma unroll
    for (int e = 0; e < NEXP; e++) red[e][tid] = acc[e];
    __syncthreads();
    for (int s = 64; s > 0; s >>= 1) {
        if (tid < s) {
#pragma unroll
            for (int e = 0; e < NEXP; e++) red[e][tid] += red[e][tid + s];
        }
        __syncthreads();
    }

    if (tid == 0) {
        float l[NEXP];
#pragma unroll
        for (int e = 0; e < NEXP; e++)
            l[e] = red[e][0] + bg[e] + NOISE_SCALE * noise[(size_t)n * NEXP + e];
        if (out_logits) {
#pragma unroll
            for (int e = 0; e < NEXP; e++)
                out_logits[(size_t)n * NEXP + e] = l[e];
        }
        int i0 = 0;
#pragma unroll
        for (int e = 1; e < NEXP; e++) if (l[e] > l[i0]) i0 = e;
        int i1 = (i0 == 0) ? 1 : 0;
#pragma unroll
        for (int e = 0; e < NEXP; e++) if (e != i0 && l[e] > l[i1]) i1 = e;

        float r = expf(l[i1] - l[i0]);
        float w0 = 1.0f / (1.0f + r);
        float w1 = r / (1.0f + r);
        g_sel[n * TOPK + 0] = i0;
        g_sel[n * TOPK + 1] = i1;
        g_wt [n * TOPK + 0] = w0;
        g_wt [n * TOPK + 1] = w1;
        if (out_sel) {
            out_sel[n * TOPK + 0] = (float)i0;
            out_sel[n * TOPK + 1] = (float)i1;
        }
    }
}

// ---------------- stable per-expert compaction -------------------------------
__global__ void build_lists_kernel() {
    int e = blockIdx.x;
    int lane = threadIdx.x;
    int c = 0;
    for (int n0 = 0; n0 < NTOK; n0 += 32) {
        int n = n0 + lane;
        int s0 = g_sel[n * TOPK + 0];
        int s1 = g_sel[n * TOPK + 1];
        bool m0 = (s0 == e), m1 = (s1 == e);
        bool any = m0 || m1;
        unsigned mask = __ballot_sync(0xffffffffu, any);
        if (any) {
            int pos = c + __popc(mask & ((1u << lane) - 1u));
            g_list[e * NTOK + pos] = n;
            g_lw  [e * NTOK + pos] = m0 ? g_wt[n * TOPK + 0] : g_wt[n * TOPK + 1];
        }
        c += __popc(mask);
    }
    if (lane == 0) g_cnt[e] = c;
}

// ---------------- GEMM1 (split-bf16 mma): act = silu(X@W1+b1)*(X@W3+b3) ------
// grid: (m=16, n=64, e=8), 256 threads. M fastest -> weight reuse in L2.
// dyn smem: A hi/lo 2-stage + B1,B3 hi/lo 2-stage = 4*ATILE + 8*BTILE elems
__global__ __launch_bounds__(256)
void gemm1_kernel(const float* __restrict__ b1, const float* __restrict__ b3) {
    int e   = blockIdx.z;
    int cnt = g_cnt[e];
    int m0  = blockIdx.x * BM;
    if (m0 >= cnt) return;
    int n0  = blockIdx.y * BN;

    extern __shared__ __align__(16) __nv_bfloat16 smem[];
    __nv_bfloat16* As_h = smem;                       // [2][ATILE]
    __nv_bfloat16* As_l = smem + 2 * ATILE;
    __nv_bfloat16* B1h  = smem + 4 * ATILE;           // [2][BTILE]
    __nv_bfloat16* B1l  = B1h + 2 * BTILE;
    __nv_bfloat16* B3h  = B1h + 4 * BTILE;
    __nv_bfloat16* B3l  = B1h + 6 * BTILE;
    __shared__ int toks[BM];

    int tid = threadIdx.x;
    if (tid < BM) {
        int r = m0 + tid;
        toks[tid] = (r < cnt) ? g_list[e * NTOK + r] : -1;
    }
    __syncthreads();

    int rowA0 = tid >> 2,          partA0 = tid & 3;
    int rowA1 = (tid + 256) >> 2,  partA1 = tid & 3;
    int tok0 = toks[rowA0]; if (tok0 < 0) tok0 = 0;   // clamped rows discarded later
    int tok1 = toks[rowA1]; if (tok1 < 0) tok1 = 0;
    int nB = tid >> 2, partB = tid & 3;

    int offA0 = rowA0 * AS_STR + partA0 * 8;
    int offA1 = rowA1 * AS_STR + partA1 * 8;
    int offB  = nB * AS_STR + partB * 8;
    size_t gA0 = (size_t)tok0 * HDIM + partA0 * 8;
    size_t gA1 = (size_t)tok1 * HDIM + partA1 * 8;
    size_t gB  = (size_t)nB * HDIM + partB * 8;

    const __nv_bfloat16* W1eh = g_w1t_h + ((size_t)e * FDIM + n0) * HDIM;
    const __nv_bfloat16* W1el = g_w1t_l + ((size_t)e * FDIM + n0) * HDIM;
    const __nv_bfloat16* W3eh = g_w3t_h + ((size_t)e * FDIM + n0) * HDIM;
    const __nv_bfloat16* W3el = g_w3t_l + ((size_t)e * FDIM + n0) * HDIM;

    unsigned uAh = (unsigned)__cvta_generic_to_shared(As_h);
    unsigned uAl = (unsigned)__cvta_generic_to_shared(As_l);
    unsigned uB1h = (unsigned)__cvta_generic_to_shared(B1h);
    unsigned uB1l = (unsigned)__cvta_generic_to_shared(B1l);
    unsigned uB3h = (unsigned)__cvta_generic_to_shared(B3h);
    unsigned uB3l = (unsigned)__cvta_generic_to_shared(B3l);

#define G1_ISSUE(s, kof)                                                        \
    do {                                                                        \
        cpa16(uAh + (unsigned)((s)*ATILE + offA0) * 2, g_xh_h + gA0 + (kof));   \
        cpa16(uAh + (unsigned)((s)*ATILE + offA1) * 2, g_xh_h + gA1 + (kof));   \
        cpa16(uAl + (unsigned)((s)*ATILE + offA0) * 2, g_xh_l + gA0 + (kof));   \
        cpa16(uAl + (unsigned)((s)*ATILE + offA1) * 2, g_xh_l + gA1 + (kof));   \
        cpa16(uB1h + (unsigned)((s)*BTILE + offB) * 2, W1eh + gB + (kof));      \
        cpa16(uB1l + (unsigned)((s)*BTILE + offB) * 2, W1el + gB + (kof));      \
        cpa16(uB3h + (unsigned)((s)*BTILE + offB) * 2, W3eh + gB + (kof));      \
        cpa16(uB3l + (unsigned)((s)*BTILE + offB) * 2, W3el + gB + (kof));      \
        CP_COMMIT();                                                            \
    } while (0)

    G1_ISSUE(0, 0);

    int lane = tid & 31, warp = tid >> 5;
    int wm = warp & 3, wn = warp >> 2;      // 4 x 2 warps -> 32x32 per warp
    int mb = wm * 32, nb = wn * 32;
    int r = lane >> 2, q = lane & 3;

    float acc1[2][4][4], acc3[2][4][4];
#pragma unroll
    for (int i = 0; i < 2; i++)
#pragma unroll
        for (int j = 0; j < 4; j++)
#pragma unroll
            for (int c = 0; c < 4; c++) { acc1[i][j][c] = 0.f; acc3[i][j][c] = 0.f; }

    int t = 0;
    for (int kk = 0; kk < HDIM; kk += BK) {
        bool nxt = (kk + BK) < HDIM;
        if (nxt) G1_ISSUE(t ^ 1, kk + BK);
        if (nxt) CP_WAIT1(); else CP_WAIT0();
        __syncthreads();

        const unsigned* Ah = (const unsigned*)(As_h + t * ATILE);
        const unsigned* Al = (const unsigned*)(As_l + t * ATILE);
        const unsigned* P1h = (const unsigned*)(B1h + t * BTILE);
        const unsigned* P1l = (const unsigned*)(B1l + t * BTILE);
        const unsigned* P3h = (const unsigned*)(B3h + t * BTILE);
        const unsigned* P3l = (const unsigned*)(B3l + t * BTILE);

#pragma unroll
        for (int k0 = 0; k0 < BK; k0 += 16) {
            int kw = k0 / 2;
            unsigned ah[2][4], al[2][4];
#pragma unroll
            for (int i = 0; i < 2; i++) {
                int row = mb + 16 * i + r;
                int i0 = row * (AS_STR / 2) + kw + q;
                int i1 = (row + 8) * (AS_STR / 2) + kw + q;
                ah[i][0] = Ah[i0]; ah[i][1] = Ah[i1]; ah[i][2] = Ah[i0 + 4]; ah[i][3] = Ah[i1 + 4];
                al[i][0] = Al[i0]; al[i][1] = Al[i1]; al[i][2] = Al[i0 + 4]; al[i][3] = Al[i1 + 4];
            }
#pragma unroll
            for (int j = 0; j < 4; j++) {
                int col = nb + 8 * j + r;
                int ib = col * (AS_STR / 2) + kw + q;
                unsigned h10 = P1h[ib], h11 = P1h[ib + 4];
                unsigned l10 = P1l[ib], l11 = P1l[ib + 4];
                unsigned h30 = P3h[ib], h31 = P3h[ib + 4];
                unsigned l30 = P3l[ib], l31 = P3l[ib + 4];
#pragma unroll
                for (int i = 0; i < 2; i++) {
                    MMA_BF16(acc1[i][j], ah[i][0], ah[i][1], ah[i][2], ah[i][3], h10, h11);
                    MMA_BF16(acc1[i][j], al[i][0], al[i][1], al[i][2], al[i][3], h10, h11);
                    MMA_BF16(acc1[i][j], ah[i][0], ah[i][1], ah[i][2], ah[i][3], l10, l11);
                    MMA_BF16(acc3[i][j], ah[i][0], ah[i][1], ah[i][2], ah[i][3], h30, h31);
                    MMA_BF16(acc3[i][j], al[i][0], al[i][1], al[i][2], al[i][3], h30, h31);
                    MMA_BF16(acc3[i][j], ah[i][0], ah[i][1], ah[i][2], ah[i][3], l30, l31);
                }
            }
        }
        __syncthreads();
        t ^= 1;
    }
#undef G1_ISSUE

    // epilogue: silu(h)*g -> split bf16 act
#pragma unroll
    for (int j = 0; j < 4; j++) {
        int col = n0 + nb + 8 * j + q * 2;
        float2 bv1 = *(const float2*)(b1 + (size_t)e * FDIM + col);
        float2 bv3 = *(const float2*)(b3 + (size_t)e * FDIM + col);
#pragma unroll
        for (int i = 0; i < 2; i++) {
#pragma unroll
            for (int h = 0; h < 2; h++) {
                int rl = mb + 16 * i + r + 8 * h;
                int rr = m0 + rl;
                if (rr < cnt) {
                    float v0 = siluf(acc1[i][j][2*h+0] + bv1.x) * (acc3[i][j][2*h+0] + bv3.x);
                    float v1 = siluf(acc1[i][j][2*h+1] + bv1.y) * (acc3[i][j][2*h+1] + bv3.y);
                    __nv_bfloat162 hv = __floats2bfloat162_rn(v0, v1);
                    unsigned oh = *reinterpret_cast<unsigned*>(&hv);
                    unsigned ol = pack2(v0 - __bfloat162float(hv.x),
                                        v1 - __bfloat162float(hv.y));
                    size_t oidx = ((size_t)e * NTOK + rr) * FDIM + col;
                    *(unsigned*)(g_act_h + oidx) = oh;
                    *(unsigned*)(g_act_l + oidx) = ol;
                }
            }
        }
    }
}

// ---------------- GEMM2 (split-bf16 mma): out[tok] += w * (act@W2 + b2) ------
// grid: (m=16, n=16, e=8), 256 threads
// dyn smem: A hi/lo 2-stage + B hi/lo 2-stage = 4*ATILE + 4*BTILE elems
__global__ __launch_bounds__(256)
void gemm2_kernel(const float* __restrict__ b2, float* __restrict__ out) {
    int e   = blockIdx.z;
    int cnt = g_cnt[e];
    int m0  = blockIdx.x * BM;
    if (m0 >= cnt) return;
    int n0  = blockIdx.y * BN;

    extern __shared__ __align__(16) __nv_bfloat16 smem[];
    __nv_bfloat16* As_h = smem;
    __nv_bfloat16* As_l = smem + 2 * ATILE;
    __nv_bfloat16* Bh   = smem + 4 * ATILE;
    __nv_bfloat16* Bl   = Bh + 2 * BTILE;
    __shared__ int   toks[BM];
    __shared__ float ws[BM];

    int tid = threadIdx.x;
    if (tid < BM) {
        int rr = m0 + tid;
        toks[tid] = (rr < cnt) ? g_list[e * NTOK + rr] : -1;
        ws[tid]   = (rr < cnt) ? g_lw  [e * NTOK + rr] : 0.0f;
    }
    __syncthreads();

    int rowA0 = tid >> 2,         partA0 = tid & 3;
    int rowA1 = (tid + 256) >> 2, partA1 = tid & 3;
    int ra0 = (m0 + rowA0 < cnt) ? rowA0 : 0;
    int ra1 = (m0 + rowA1 < cnt) ? rowA1 : 0;
    int nB = tid >> 2, partB = tid & 3;

    int offA0 = rowA0 * AS_STR + partA0 * 8;
    int offA1 = rowA1 * AS_STR + partA1 * 8;
    int offB  = nB * AS_STR + partB * 8;
    const __nv_bfloat16* Aeh = g_act_h + ((size_t)e * NTOK + m0) * FDIM;
    const __nv_bfloat16* Ael = g_act_l + ((size_t)e * NTOK + m0) * FDIM;
    size_t gA0 = (size_t)ra0 * FDIM + partA0 * 8;
    size_t gA1 = (size_t)ra1 * FDIM + partA1 * 8;
    size_t gB  = (size_t)nB * FDIM + partB * 8;
    const __nv_bfloat16* W2eh = g_w2t_h + ((size_t)e * HDIM + n0) * FDIM;
    const __nv_bfloat16* W2el = g_w2t_l + ((size_t)e * HDIM + n0) * FDIM;

    unsigned uAh = (unsigned)__cvta_generic_to_shared(As_h);
    unsigned uAl = (unsigned)__cvta_generic_to_shared(As_l);
    unsigned uBh = (unsigned)__cvta_generic_to_shared(Bh);
    unsigned uBl = (unsigned)__cvta_generic_to_shared(Bl);

#define G2_ISSUE(s, kof)                                                        \
    do {                                                                        \
        cpa16(uAh + (unsigned)((s)*ATILE + offA0) * 2, Aeh + gA0 + (kof));      \
        cpa16(uAh + (unsigned)((s)*ATILE + offA1) * 2, Aeh + gA1 + (kof));      \
        cpa16(uAl + (unsigned)((s)*ATILE + offA0) * 2, Ael + gA0 + (kof));      \
        cpa16(uAl + (unsigned)((s)*ATILE + offA1) * 2, Ael + gA1 + (kof));      \
        cpa16(uBh + (unsigned)((s)*BTILE + offB) * 2, W2eh + gB + (kof));       \
        cpa16(uBl + (unsigned)((s)*BTILE + offB) * 2, W2el + gB + (kof));       \
        CP_COMMIT();                                                            \
    } while (0)

    G2_ISSUE(0, 0);

    int lane = tid & 31, warp = tid >> 5;
    int wm = warp & 3, wn = warp >> 2;
    int mb = wm * 32, nb = wn * 32;
    int r = lane >> 2, q = lane & 3;

    float acc[2][4][4];
#pragma unroll
    for (int i = 0; i < 2; i++)
#pragma unroll
        for (int j = 0; j < 4; j++)
#pragma unroll
            for (int c = 0; c < 4; c++) acc[i][j][c] = 0.f;

    int t = 0;
    for (int kk = 0; kk < FDIM; kk += BK) {
        bool nxt = (kk + BK) < FDIM;
        if (nxt) G2_ISSUE(t ^ 1, kk + BK);
        if (nxt) CP_WAIT1(); else CP_WAIT0();
        __syncthreads();

        const unsigned* Ah = (const unsigned*)(As_h + t * ATILE);
        const unsigned* Al = (const unsigned*)(As_l + t * ATILE);
        const unsigned* Ph = (const unsigned*)(Bh + t * BTILE);
        const unsigned* Pl = (const unsigned*)(Bl + t * BTILE);

#pragma unroll
        for (int k0 = 0; k0 < BK; k0 += 16) {
            int kw = k0 / 2;
            unsigned ah[2][4], al[2][4];
#pragma unroll
            for (int i = 0; i < 2; i++) {
                int row = mb + 16 * i + r;
                int i0 = row * (AS_STR / 2) + kw + q;
                int i1 = (row + 8) * (AS_STR / 2) + kw + q;
                ah[i][0] = Ah[i0]; ah[i][1] = Ah[i1]; ah[i][2] = Ah[i0 + 4]; ah[i][3] = Ah[i1 + 4];
                al[i][0] = Al[i0]; al[i][1] = Al[i1]; al[i][2] = Al[i0 + 4]; al[i][3] = Al[i1 + 4];
            }
#pragma unroll
            for (int j = 0; j < 4; j++) {
                int col = nb + 8 * j + r;
                int ib = col * (AS_STR / 2) + kw + q;
                unsigned bh0 = Ph[ib], bh1 = Ph[ib + 4];
                unsigned bl0 = Pl[ib], bl1 = Pl[ib + 4];
#pragma unroll
                for (int i = 0; i < 2; i++) {
                    MMA_BF16(acc[i][j], ah[i][0], ah[i][1], ah[i][2], ah[i][3], bh0, bh1);
                    MMA_BF16(acc[i][j], al[i][0], al[i][1], al[i][2], al[i][3], bh0, bh1);
                    MMA_BF16(acc[i][j], ah[i][0], ah[i][1], ah[i][2], ah[i][3], bl0, bl1);
                }
            }
        }
        __syncthreads();
        t ^= 1;
    }
#undef G2_ISSUE

#pragma unroll
    for (int j = 0; j < 4; j++) {
        int col = n0 + nb + 8 * j + q * 2;
        float2 bv = *(const float2*)(b2 + (size_t)e * HDIM + col);
#pragma unroll
        for (int i = 0; i < 2; i++) {
#pragma unroll
            for (int h = 0; h < 2; h++) {
                int rl = mb + 16 * i + r + 8 * h;
                int rr = m0 + rl;
                if (rr < cnt) {
                    int tok = toks[rl];
                    float w = ws[rl];
                    float* op = out + (size_t)tok * HDIM + col;
                    atomicAdd(op + 0, w * (acc[i][j][2*h+0] + bv.x));
                    atomicAdd(op + 1, w * (acc[i][j][2*h+1] + bv.y));
                }
            }
        }
    }
}

// ---------------- launch -----------------------------------------------------
extern "C" void kernel_launch(void* const* d_in, const int* in_sizes, int n_in,
                              void* d_out, int out_size) {
    const float* x     = (const float*)d_in[0];
    const float* noise = (const float*)d_in[1];
    const float* Wg    = (const float*)d_in[2];
    const float* bg    = (const float*)d_in[3];
    const float* W1    = (const float*)d_in[4];
    const float* b1    = (const float*)d_in[5];
    const float* W2    = (const float*)d_in[6];
    const float* b2    = (const float*)d_in[7];
    const float* W3    = (const float*)d_in[8];
    const float* b3    = (const float*)d_in[9];

    float* out = (float*)d_out;
    const size_t HID = (size_t)NTOK * HDIM;
    const size_t LOG = (size_t)NTOK * NEXP;
    const size_t SEL = (size_t)NTOK * TOPK;

    float* out_logits = nullptr;
    float* out_sel    = nullptr;
    if ((size_t)out_size >= HID + LOG)       out_logits = out + HID;
    if ((size_t)out_size >= HID + LOG + SEL) out_sel    = out + HID + LOG;

    cudaMemsetAsync(out, 0, HID * sizeof(float));

    convert_x_kernel<<<(NTOK * HDIM / 4) / 256, 256>>>(x);
    {
        __nv_bfloat16 *w1h, *w1l, *w3h, *w3l, *w2h, *w2l;
        cudaGetSymbolAddress((void**)&w1h, g_w1t_h);
        cudaGetSymbolAddress((void**)&w1l, g_w1t_l);
        cudaGetSymbolAddress((void**)&w3h, g_w3t_h);
        cudaGetSymbolAddress((void**)&w3l, g_w3t_l);
        cudaGetSymbolAddress((void**)&w2h, g_w2t_h);
        cudaGetSymbolAddress((void**)&w2l, g_w2t_l);
        dim3 blk(32, 8);
        dim3 gA(FDIM / 32, HDIM / 32, NEXP);   // W1,W3: K=H, N=F
        dim3 gB(HDIM / 32, FDIM / 32, NEXP);   // W2:    K=F, N=H
        transpose_convert_kernel<<<gA, blk>>>(W1, w1h, w1l, HDIM, FDIM);
        transpose_convert_kernel<<<gA, blk>>>(W3, w3h, w3l, HDIM, FDIM);
        transpose_convert_kernel<<<gB, blk>>>(W2, w2h, w2l, FDIM, HDIM);
    }

    router_kernel<<<NTOK, 128>>>(x, noise, Wg, bg, out_logits, out_sel);
    build_lists_kernel<<<NEXP, 32>>>();

    const int smem1 = (4 * ATILE + 8 * BTILE) * sizeof(__nv_bfloat16);  // 81920
    const int smem2 = (4 * ATILE + 4 * BTILE) * sizeof(__nv_bfloat16);  // 61440
    cudaFuncSetAttribute(gemm1_kernel, cudaFuncAttributeMaxDynamicSharedMemorySize, smem1);
    cudaFuncSetAttribute(gemm2_kernel, cudaFuncAttributeMaxDynamicSharedMemorySize, smem2);

    dim3 g1(NTOK / BM, FDIM / BN, NEXP);   // (16, 64, 8), M fastest
    gemm1_kernel<<<g1, 256, smem1>>>(b1, b3);

    dim3 g2(NTOK / BM, HDIM / BN, NEXP);   // (16, 16, 8)
    gemm2_kernel<<<g2, 256, smem2>>>(b2, out);
}

// round 9
// speedup vs baseline: 3.2860x; 1.6922x over previous
#include <cuda_runtime.h>
#include <cuda_fp16.h>
#include <math.h>
#include <stdint.h>

// Problem shape (fixed)
#define NTOK 2048      // B*T
#define HDIM 1024      // H
#define FDIM 4096      // F
#define NEXP 8         // E
#define TOPK 2
#define NOISE_SCALE 0.01f

// GEMM tiling
#define BM 128
#define BN 64
#define BK 64
#define AS_STR 72              // BK + 8 pad (fp16 elems); 36 words/row
#define ATILE (BM * AS_STR)    // 9216 elems
#define BTILE (BN * AS_STR)    // 4608 elems
#define NSTG 3                 // pipeline stages (prefetch distance 2)

// ---------------- device scratch (allocation-free) ---------------------------
__device__ int   g_sel[NTOK * TOPK];
__device__ float g_wt [NTOK * TOPK];
__device__ int   g_cnt[NEXP];
__device__ int   g_list[NEXP * NTOK];
__device__ float g_lw  [NEXP * NTOK];

// fp16 weights transposed to [E][N][K]; fp16 x and activations
__device__ __align__(16) __half g_w1t[(size_t)NEXP * FDIM * HDIM];
__device__ __align__(16) __half g_w3t[(size_t)NEXP * FDIM * HDIM];
__device__ __align__(16) __half g_w2t[(size_t)NEXP * HDIM * FDIM];
__device__ __align__(16) __half g_x16[(size_t)NTOK * HDIM];
__device__ __align__(16) __half g_act[(size_t)NEXP * NTOK * FDIM];

__device__ __forceinline__ float siluf(float v) { return v / (1.0f + expf(-v)); }

#define MMA_F16(d, a0,a1,a2,a3, b0,b1)                                           \
    asm volatile("mma.sync.aligned.m16n8k16.row.col.f32.f16.f16.f32 "            \
                 "{%0,%1,%2,%3},{%4,%5,%6,%7},{%8,%9},{%0,%1,%2,%3};\n"          \
                 : "+f"(d[0]), "+f"(d[1]), "+f"(d[2]), "+f"(d[3])                \
                 : "r"(a0), "r"(a1), "r"(a2), "r"(a3), "r"(b0), "r"(b1))

__device__ __forceinline__ void cpa16(unsigned dst, const void* src) {
    asm volatile("cp.async.ca.shared.global [%0], [%1], 16;\n" :: "r"(dst), "l"(src));
}
#define CP_COMMIT() asm volatile("cp.async.commit_group;\n")
#define CP_WAIT0()  asm volatile("cp.async.wait_group 0;\n")
#define CP_WAIT1()  asm volatile("cp.async.wait_group 1;\n")

// ---------------- conversion: x fp32 -> fp16 ---------------------------------
__global__ void convert_x_kernel(const float* __restrict__ x) {
    int i = blockIdx.x * blockDim.x + threadIdx.x;   // one float4 per thread
    float4 v = reinterpret_cast<const float4*>(x)[i];
    __half2 h0 = __floats2half2_rn(v.x, v.y);
    __half2 h1 = __floats2half2_rn(v.z, v.w);
    uint2 o;
    o.x = *reinterpret_cast<unsigned*>(&h0);
    o.y = *reinterpret_cast<unsigned*>(&h1);
    reinterpret_cast<uint2*>(g_x16)[i] = o;
}

// ---------------- transpose+convert: W[e][K][N] f32 -> fp16 [e][N][K] --------
__global__ void transpose_convert_kernel(const float* __restrict__ W,
                                         __half* __restrict__ Wt,
                                         int K, int N) {
    __shared__ float tile[32][33];
    int e = blockIdx.z;
    const float* We = W + (size_t)e * K * N;
    int n0 = blockIdx.x * 32, k0 = blockIdx.y * 32;
    int tx = threadIdx.x, ty = threadIdx.y;   // 32 x 8
#pragma unroll
    for (int j = 0; j < 32; j += 8)
        tile[ty + j][tx] = We[(size_t)(k0 + ty + j) * N + n0 + tx];
    __syncthreads();
    size_t base = (size_t)e * K * N;
#pragma unroll
    for (int j = 0; j < 32; j += 8)
        Wt[base + (size_t)(n0 + ty + j) * K + k0 + tx] = __float2half(tile[tx][ty + j]);
}

// ---------------- router -----------------------------------------------------
__global__ void router_kernel(const float* __restrict__ x,
                              const float* __restrict__ noise,
                              const float* __restrict__ Wg,
                              const float* __restrict__ bg,
                              float* out_logits, float* out_sel) {
    int n = blockIdx.x;
    int tid = threadIdx.x;          // 128
    const float* xr = x + (size_t)n * HDIM;

    float acc[NEXP];
#pragma unroll
    for (int e = 0; e < NEXP; e++) acc[e] = 0.0f;
    for (int h = tid; h < HDIM; h += 128) {
        float xv = xr[h];
        const float* wr = Wg + (size_t)h * NEXP;
#pragma unroll
        for (int e = 0; e < NEXP; e++) acc[e] += xv * wr[e];
    }

    __shared__ float red[NEXP][128];
#pragma unroll
    for (int e = 0; e < NEXP; e++) red[e][tid] = acc[e];
    __syncthreads();
    for (int s = 64; s > 0; s >>= 1) {
        if (tid < s) {
#pragma unroll
            for (int e = 0; e < NEXP; e++) red[e][tid] += red[e][tid + s];
        }
        __syncthreads();
    }

    if (tid == 0) {
        float l[NEXP];
#pragma unroll
        for (int e = 0; e < NEXP; e++)
            l[e] = red[e][0] + bg[e] + NOISE_SCALE * noise[(size_t)n * NEXP + e];
        if (out_logits) {
#pragma unroll
            for (int e = 0; e < NEXP; e++)
                out_logits[(size_t)n * NEXP + e] = l[e];
        }
        int i0 = 0;
#pragma unroll
        for (int e = 1; e < NEXP; e++) if (l[e] > l[i0]) i0 = e;
        int i1 = (i0 == 0) ? 1 : 0;
#pragma unroll
        for (int e = 0; e < NEXP; e++) if (e != i0 && l[e] > l[i1]) i1 = e;

        float r = expf(l[i1] - l[i0]);
        float w0 = 1.0f / (1.0f + r);
        float w1 = r / (1.0f + r);
        g_sel[n * TOPK + 0] = i0;
        g_sel[n * TOPK + 1] = i1;
        g_wt [n * TOPK + 0] = w0;
        g_wt [n * TOPK + 1] = w1;
        if (out_sel) {
            out_sel[n * TOPK + 0] = (float)i0;
            out_sel[n * TOPK + 1] = (float)i1;
        }
    }
}

// ---------------- stable per-expert compaction -------------------------------
__global__ void build_lists_kernel() {
    int e = blockIdx.x;
    int lane = threadIdx.x;
    int c = 0;
    for (int n0 = 0; n0 < NTOK; n0 += 32) {
        int n = n0 + lane;
        int s0 = g_sel[n * TOPK + 0];
        int s1 = g_sel[n * TOPK + 1];
        bool m0 = (s0 == e), m1 = (s1 == e);
        bool any = m0 || m1;
        unsigned mask = __ballot_sync(0xffffffffu, any);
        if (any) {
            int pos = c + __popc(mask & ((1u << lane) - 1u));
            g_list[e * NTOK + pos] = n;
            g_lw  [e * NTOK + pos] = m0 ? g_wt[n * TOPK + 0] : g_wt[n * TOPK + 1];
        }
        c += __popc(mask);
    }
    if (lane == 0) g_cnt[e] = c;
}

// ---------------- GEMM1 (fp16 mma): act = silu(X@W1+b1)*(X@W3+b3) ------------
// grid: (m=16, n=64, e=8), 256 threads, 3-stage cp.async (distance-2 prefetch)
// dyn smem: 3 stages * (ATILE + 2*BTILE) halves = 110592 B
__global__ __launch_bounds__(256, 1)
void gemm1_kernel(const float* __restrict__ b1, const float* __restrict__ b3) {
    int e   = blockIdx.z;
    int cnt = g_cnt[e];
    int m0  = blockIdx.x * BM;
    if (m0 >= cnt) return;
    int n0  = blockIdx.y * BN;

    extern __shared__ __align__(16) __half smem[];
    const int STG = ATILE + 2 * BTILE;    // halves per stage
    __shared__ int toks[BM];

    int tid = threadIdx.x;
    if (tid < BM) {
        int r = m0 + tid;
        toks[tid] = (r < cnt) ? g_list[e * NTOK + r] : -1;
    }
    __syncthreads();

    // staging: A 1024 chunks (4/thread), B1 512 (2/thread), B3 512 (2/thread)
    int arow = tid >> 1, apart = (tid & 1) * 4;       // 4 consecutive 16B parts
    int tokA = toks[arow]; if (tokA < 0) tokA = 0;
    int brow = tid >> 2, bpart = (tid & 3) * 2;       // 2 consecutive parts

    const __half* pA  = g_x16 + (size_t)tokA * HDIM + apart * 8;
    const __half* pB1 = g_w1t + ((size_t)e * FDIM + n0 + brow) * HDIM + bpart * 8;
    const __half* pB3 = g_w3t + ((size_t)e * FDIM + n0 + brow) * HDIM + bpart * 8;

    unsigned uA  = (unsigned)__cvta_generic_to_shared(smem)
                   + (unsigned)(arow * AS_STR + apart * 8) * 2;
    unsigned uB1 = (unsigned)__cvta_generic_to_shared(smem + ATILE)
                   + (unsigned)(brow * AS_STR + bpart * 8) * 2;
    unsigned uB3 = (unsigned)__cvta_generic_to_shared(smem + ATILE + BTILE)
                   + (unsigned)(brow * AS_STR + bpart * 8) * 2;

#define G1_ISSUE(s, kof)                                                         \
    do {                                                                         \
        unsigned sb_ = (unsigned)(s) * STG * 2;                                  \
        cpa16(uA  + sb_,      pA  + (kof));                                      \
        cpa16(uA  + sb_ + 16, pA  + (kof) + 8);                                  \
        cpa16(uA  + sb_ + 32, pA  + (kof) + 16);                                 \
        cpa16(uA  + sb_ + 48, pA  + (kof) + 24);                                 \
        cpa16(uB1 + sb_,      pB1 + (kof));                                      \
        cpa16(uB1 + sb_ + 16, pB1 + (kof) + 8);                                  \
        cpa16(uB3 + sb_,      pB3 + (kof));                                      \
        cpa16(uB3 + sb_ + 16, pB3 + (kof) + 8);                                  \
        CP_COMMIT();                                                             \
    } while (0)

    // preload stages 0,1 (iterations 0,1)
    G1_ISSUE(0, 0);
    G1_ISSUE(1, BK);

    int lane = tid & 31, warp = tid >> 5;
    int wm = warp & 3, wn = warp >> 2;      // 4 x 2 warps -> 32x32 each
    int mb = wm * 32, nb = wn * 32;
    int r = lane >> 2, q = lane & 3;

    float acc1[2][4][4], acc3[2][4][4];
#pragma unroll
    for (int i = 0; i < 2; i++)
#pragma unroll
        for (int j = 0; j < 4; j++)
#pragma unroll
            for (int c = 0; c < 4; c++) { acc1[i][j][c] = 0.f; acc3[i][j][c] = 0.f; }

    const int NIT = HDIM / BK;   // 16
    for (int it = 0; it < NIT; it++) {
        if (it < NIT - 1) CP_WAIT1(); else CP_WAIT0();
        __syncthreads();
        // prefetch iteration it+2 into stage (it+2)%3: that buffer was last
        // READ at iteration it-1, and the sync above proves all warps are done
        // with it -> no WAR race.
        if (it + 2 < NIT) G1_ISSUE((it + 2) % NSTG, (it + 2) * BK);

        int st = it % NSTG;
        const unsigned* A32 = (const unsigned*)(smem + st * STG);
        const unsigned* P1  = (const unsigned*)(smem + st * STG + ATILE);
        const unsigned* P3  = (const unsigned*)(smem + st * STG + ATILE + BTILE);

#pragma unroll
        for (int k0 = 0; k0 < BK; k0 += 16) {
            int kw = k0 / 2;
            unsigned a[2][4];
#pragma unroll
            for (int i = 0; i < 2; i++) {
                int row = mb + 16 * i + r;
                int i0 = row * (AS_STR / 2) + kw + q;
                int i1 = (row + 8) * (AS_STR / 2) + kw + q;
                a[i][0] = A32[i0]; a[i][1] = A32[i1];
                a[i][2] = A32[i0 + 4]; a[i][3] = A32[i1 + 4];
            }
#pragma unroll
            for (int j = 0; j < 4; j++) {
                int col = nb + 8 * j + r;
                int ib = col * (AS_STR / 2) + kw + q;
                unsigned b10 = P1[ib], b11 = P1[ib + 4];
                unsigned b30 = P3[ib], b31 = P3[ib + 4];
#pragma unroll
                for (int i = 0; i < 2; i++) {
                    MMA_F16(acc1[i][j], a[i][0], a[i][1], a[i][2], a[i][3], b10, b11);
                    MMA_F16(acc3[i][j], a[i][0], a[i][1], a[i][2], a[i][3], b30, b31);
                }
            }
        }
    }
#undef G1_ISSUE

    // epilogue: silu(h)*g -> fp16 act
#pragma unroll
    for (int j = 0; j < 4; j++) {
        int col = n0 + nb + 8 * j + q * 2;
        float2 bv1 = *(const float2*)(b1 + (size_t)e * FDIM + col);
        float2 bv3 = *(const float2*)(b3 + (size_t)e * FDIM + col);
#pragma unroll
        for (int i = 0; i < 2; i++) {
#pragma unroll
            for (int h = 0; h < 2; h++) {
                int rl = mb + 16 * i + r + 8 * h;
                int rr = m0 + rl;
                if (rr < cnt) {
                    float v0 = siluf(acc1[i][j][2*h+0] + bv1.x) * (acc3[i][j][2*h+0] + bv3.x);
                    float v1 = siluf(acc1[i][j][2*h+1] + bv1.y) * (acc3[i][j][2*h+1] + bv3.y);
                    __half2 hv = __floats2half2_rn(v0, v1);
                    *(__half2*)(g_act + ((size_t)e * NTOK + rr) * FDIM + col) = hv;
                }
            }
        }
    }
}

// ---------------- GEMM2 (fp16 mma): out[tok] += w * (act@W2 + b2) ------------
// grid: (m=16, n=16, e=8), 256 threads, 3-stage pipeline
// dyn smem: 3 stages * (ATILE + BTILE) halves = 82944 B
__global__ __launch_bounds__(256, 1)
void gemm2_kernel(const float* __restrict__ b2, float* __restrict__ out) {
    int e   = blockIdx.z;
    int cnt = g_cnt[e];
    int m0  = blockIdx.x * BM;
    if (m0 >= cnt) return;
    int n0  = blockIdx.y * BN;

    extern __shared__ __align__(16) __half smem[];
    const int STG = ATILE + BTILE;
    __shared__ int   toks[BM];
    __shared__ float ws[BM];

    int tid = threadIdx.x;
    if (tid < BM) {
        int rr = m0 + tid;
        toks[tid] = (rr < cnt) ? g_list[e * NTOK + rr] : -1;
        ws[tid]   = (rr < cnt) ? g_lw  [e * NTOK + rr] : 0.0f;
    }
    __syncthreads();

    int arow = tid >> 1, apart = (tid & 1) * 4;
    int ra = (m0 + arow < cnt) ? arow : 0;
    int brow = tid >> 2, bpart = (tid & 3) * 2;

    const __half* pA = g_act + ((size_t)e * NTOK + m0 + ra) * FDIM + apart * 8;
    const __half* pB = g_w2t + ((size_t)e * HDIM + n0 + brow) * FDIM + bpart * 8;

    unsigned uA = (unsigned)__cvta_generic_to_shared(smem)
                  + (unsigned)(arow * AS_STR + apart * 8) * 2;
    unsigned uB = (unsigned)__cvta_generic_to_shared(smem + ATILE)
                  + (unsigned)(brow * AS_STR + bpart * 8) * 2;

#define G2_ISSUE(s, kof)                                                         \
    do {                                                                         \
        unsigned sb_ = (unsigned)(s) * STG * 2;                                  \
        cpa16(uA + sb_,      pA + (kof));                                        \
        cpa16(uA + sb_ + 16, pA + (kof) + 8);                                    \
        cpa16(uA + sb_ + 32, pA + (kof) + 16);                                   \
        cpa16(uA + sb_ + 48, pA + (kof) + 24);                                   \
        cpa16(uB + sb_,      pB + (kof));                                        \
        cpa16(uB + sb_ + 16, pB + (kof) + 8);                                    \
        CP_COMMIT();                                                             \
    } while (0)

    G2_ISSUE(0, 0);
    G2_ISSUE(1, BK);

    int lane = tid & 31, warp = tid >> 5;
    int wm = warp & 3, wn = warp >> 2;
    int mb = wm * 32, nb = wn * 32;
    int r = lane >> 2, q = lane & 3;

    float acc[2][4][4];
#pragma unroll
    for (int i = 0; i < 2; i++)
#pragma unroll
        for (int j = 0; j < 4; j++)
#pragma unroll
            for (int c = 0; c < 4; c++) acc[i][j][c] = 0.f;

    const int NIT = FDIM / BK;   // 64
    for (int it = 0; it < NIT; it++) {
        if (it < NIT - 1) CP_WAIT1(); else CP_WAIT0();
        __syncthreads();
        if (it + 2 < NIT) G2_ISSUE((it + 2) % NSTG, (it + 2) * BK);

        int st = it % NSTG;
        const unsigned* A32 = (const unsigned*)(smem + st * STG);
        const unsigned* B32 = (const unsigned*)(smem + st * STG + ATILE);

#pragma unroll
        for (int k0 = 0; k0 < BK; k0 += 16) {
            int kw = k0 / 2;
            unsigned a[2][4];
#pragma unroll
            for (int i = 0; i < 2; i++) {
                int row = mb + 16 * i + r;
                int i0 = row * (AS_STR / 2) + kw + q;
                int i1 = (row + 8) * (AS_STR / 2) + kw + q;
                a[i][0] = A32[i0]; a[i][1] = A32[i1];
                a[i][2] = A32[i0 + 4]; a[i][3] = A32[i1 + 4];
            }
#pragma unroll
            for (int j = 0; j < 4; j++) {
                int col = nb + 8 * j + r;
                int ib = col * (AS_STR / 2) + kw + q;
                unsigned b0 = B32[ib], b1r = B32[ib + 4];
#pragma unroll
                for (int i = 0; i < 2; i++)
                    MMA_F16(acc[i][j], a[i][0], a[i][1], a[i][2], a[i][3], b0, b1r);
            }
        }
    }
#undef G2_ISSUE

#pragma unroll
    for (int j = 0; j < 4; j++) {
        int col = n0 + nb + 8 * j + q * 2;
        float2 bv = *(const float2*)(b2 + (size_t)e * HDIM + col);
#pragma unroll
        for (int i = 0; i < 2; i++) {
#pragma unroll
            for (int h = 0; h < 2; h++) {
                int rl = mb + 16 * i + r + 8 * h;
                int rr = m0 + rl;
                if (rr < cnt) {
                    int tok = toks[rl];
                    float w = ws[rl];
                    float* op = out + (size_t)tok * HDIM + col;
                    atomicAdd(op + 0, w * (acc[i][j][2*h+0] + bv.x));
                    atomicAdd(op + 1, w * (acc[i][j][2*h+1] + bv.y));
                }
            }
        }
    }
}

// ---------------- launch -----------------------------------------------------
extern "C" void kernel_launch(void* const* d_in, const int* in_sizes, int n_in,
                              void* d_out, int out_size) {
    const float* x     = (const float*)d_in[0];
    const float* noise = (const float*)d_in[1];
    const float* Wg    = (const float*)d_in[2];
    const float* bg    = (const float*)d_in[3];
    const float* W1    = (const float*)d_in[4];
    const float* b1    = (const float*)d_in[5];
    const float* W2    = (const float*)d_in[6];
    const float* b2    = (const float*)d_in[7];
    const float* W3    = (const float*)d_in[8];
    const float* b3    = (const float*)d_in[9];

    float* out = (float*)d_out;
    const size_t HID = (size_t)NTOK * HDIM;
    const size_t LOG = (size_t)NTOK * NEXP;
    const size_t SEL = (size_t)NTOK * TOPK;

    float* out_logits = nullptr;
    float* out_sel    = nullptr;
    if ((size_t)out_size >= HID + LOG)       out_logits = out + HID;
    if ((size_t)out_size >= HID + LOG + SEL) out_sel    = out + HID + LOG;

    cudaMemsetAsync(out, 0, HID * sizeof(float));

    convert_x_kernel<<<(NTOK * HDIM / 4) / 256, 256>>>(x);
    {
        __half *w1t, *w3t, *w2t;
        cudaGetSymbolAddress((void**)&w1t, g_w1t);
        cudaGetSymbolAddress((void**)&w3t, g_w3t);
        cudaGetSymbolAddress((void**)&w2t, g_w2t);
        dim3 blk(32, 8);
        dim3 gA(FDIM / 32, HDIM / 32, NEXP);   // W1,W3: K=H, N=F
        dim3 gB(HDIM / 32, FDIM / 32, NEXP);   // W2:    K=F, N=H
        transpose_convert_kernel<<<gA, blk>>>(W1, w1t, HDIM, FDIM);
        transpose_convert_kernel<<<gA, blk>>>(W3, w3t, HDIM, FDIM);
        transpose_convert_kernel<<<gB, blk>>>(W2, w2t, FDIM, HDIM);
    }

    router_kernel<<<NTOK, 128>>>(x, noise, Wg, bg, out_logits, out_sel);
    build_lists_kernel<<<NEXP, 32>>>();

    const int smem1 = NSTG * (ATILE + 2 * BTILE) * sizeof(__half);  // 110592
    const int smem2 = NSTG * (ATILE + BTILE) * sizeof(__half);      // 82944
    cudaFuncSetAttribute(gemm1_kernel, cudaFuncAttributeMaxDynamicSharedMemorySize, smem1);
    cudaFuncSetAttribute(gemm2_kernel, cudaFuncAttributeMaxDynamicSharedMemorySize, smem2);

    dim3 g1(NTOK / BM, FDIM / BN, NEXP);   // (16, 64, 8), M fastest
    gemm1_kernel<<<g1, 256, smem1>>>(b1, b3);

    dim3 g2(NTOK / BM, HDIM / BN, NEXP);   // (16, 16, 8)
    gemm2_kernel<<<g2, 256, smem2>>>(b2, out);
}

// round 10
// speedup vs baseline: 3.5940x; 1.0937x over previous
#include <cuda_runtime.h>
#include <cuda_fp16.h>
#include <math.h>
#include <stdint.h>

// Problem shape (fixed)
#define NTOK 2048      // B*T
#define HDIM 1024      // H
#define FDIM 4096      // F
#define NEXP 8         // E
#define TOPK 2
#define NOISE_SCALE 0.01f

// GEMM tiling
#define BM 128
#define BN 64
#define BK 64
#define AS_STR 72              // BK + 8 pad (fp16 elems); row stride 144 B (16-aligned)
#define ATILE (BM * AS_STR)    // 9216 elems
#define BTILE (BN * AS_STR)    // 4608 elems
#define NSTG 3                 // pipeline stages (prefetch distance 2)

// ---------------- device scratch (allocation-free) ---------------------------
__device__ int   g_sel[NTOK * TOPK];
__device__ float g_wt [NTOK * TOPK];
__device__ int   g_cnt[NEXP];
__device__ int   g_list[NEXP * NTOK];
__device__ float g_lw  [NEXP * NTOK];

// fp16 weights transposed to [E][N][K]; fp16 x and activations
__device__ __align__(16) __half g_w1t[(size_t)NEXP * FDIM * HDIM];
__device__ __align__(16) __half g_w3t[(size_t)NEXP * FDIM * HDIM];
__device__ __align__(16) __half g_w2t[(size_t)NEXP * HDIM * FDIM];
__device__ __align__(16) __half g_x16[(size_t)NTOK * HDIM];
__device__ __align__(16) __half g_act[(size_t)NEXP * NTOK * FDIM];

__device__ __forceinline__ float siluf(float v) { return v / (1.0f + expf(-v)); }

#define MMA_F16(d, a0,a1,a2,a3, b0,b1)                                           \
    asm volatile("mma.sync.aligned.m16n8k16.row.col.f32.f16.f16.f32 "            \
                 "{%0,%1,%2,%3},{%4,%5,%6,%7},{%8,%9},{%0,%1,%2,%3};\n"          \
                 : "+f"(d[0]), "+f"(d[1]), "+f"(d[2]), "+f"(d[3])                \
                 : "r"(a0), "r"(a1), "r"(a2), "r"(a3), "r"(b0), "r"(b1))

#define LDSM4(r0,r1,r2,r3, addr)                                                 \
    asm volatile("ldmatrix.sync.aligned.m8n8.x4.shared.b16 {%0,%1,%2,%3}, [%4];" \
                 : "=r"(r0), "=r"(r1), "=r"(r2), "=r"(r3) : "r"(addr))

__device__ __forceinline__ void cpa16(unsigned dst, const void* src) {
    asm volatile("cp.async.ca.shared.global [%0], [%1], 16;\n" :: "r"(dst), "l"(src));
}
#define CP_COMMIT() asm volatile("cp.async.commit_group;\n")
#define CP_WAIT0()  asm volatile("cp.async.wait_group 0;\n")
#define CP_WAIT1()  asm volatile("cp.async.wait_group 1;\n")

// ---------------- conversion: x fp32 -> fp16 ---------------------------------
__global__ void convert_x_kernel(const float* __restrict__ x) {
    int i = blockIdx.x * blockDim.x + threadIdx.x;   // one float4 per thread
    float4 v = reinterpret_cast<const float4*>(x)[i];
    __half2 h0 = __floats2half2_rn(v.x, v.y);
    __half2 h1 = __floats2half2_rn(v.z, v.w);
    uint2 o;
    o.x = *reinterpret_cast<unsigned*>(&h0);
    o.y = *reinterpret_cast<unsigned*>(&h1);
    reinterpret_cast<uint2*>(g_x16)[i] = o;
}

// ---------------- fused transpose+convert for W1, W3, W2 ---------------------
// W[e][K][N] f32 -> Wt[e][N][K] fp16; z = mat*NEXP + e; grid.x = (K/32)*(N/32)=4096
__global__ void transpose_convert_all(const float* __restrict__ W1,
                                      const float* __restrict__ W3,
                                      const float* __restrict__ W2) {
    __shared__ float tile[32][33];
    int z = blockIdx.z;
    int mat = z >> 3;          // 0:W1, 1:W3, 2:W2
    int e   = z & 7;
    const float* W;
    __half* Wt;
    int K, N;
    if (mat == 0)      { W = W1; Wt = g_w1t; K = HDIM; N = FDIM; }
    else if (mat == 1) { W = W3; Wt = g_w3t; K = HDIM; N = FDIM; }
    else               { W = W2; Wt = g_w2t; K = FDIM; N = HDIM; }

    int ntn = N >> 5;
    int n0 = (blockIdx.x % ntn) << 5;
    int k0 = (blockIdx.x / ntn) << 5;

    const float* We = W + (size_t)e * K * N;
    int tx = threadIdx.x, ty = threadIdx.y;   // 32 x 8
#pragma unroll
    for (int j = 0; j < 32; j += 8)
        tile[ty + j][tx] = We[(size_t)(k0 + ty + j) * N + n0 + tx];
    __syncthreads();
    size_t base = (size_t)e * K * N;
#pragma unroll
    for (int j = 0; j < 32; j += 8)
        Wt[base + (size_t)(n0 + ty + j) * K + k0 + tx] = __float2half(tile[tx][ty + j]);
}

// ---------------- router -----------------------------------------------------
__global__ void router_kernel(const float* __restrict__ x,
                              const float* __restrict__ noise,
                              const float* __restrict__ Wg,
                              const float* __restrict__ bg,
                              float* out_logits, float* out_sel) {
    int n = blockIdx.x;
    int tid = threadIdx.x;          // 128
    const float* xr = x + (size_t)n * HDIM;

    float acc[NEXP];
#pragma unroll
    for (int e = 0; e < NEXP; e++) acc[e] = 0.0f;
    for (int h = tid; h < HDIM; h += 128) {
        float xv = xr[h];
        const float* wr = Wg + (size_t)h * NEXP;
#pragma unroll
        for (int e = 0; e < NEXP; e++) acc[e] += xv * wr[e];
    }

    __shared__ float red[NEXP][128];
#pragma unroll
    for (int e = 0; e < NEXP; e++) red[e][tid] = acc[e];
    __syncthreads();
    for (int s = 64; s > 0; s >>= 1) {
        if (tid < s) {
#pragma unroll
            for (int e = 0; e < NEXP; e++) red[e][tid] += red[e][tid + s];
        }
        __syncthreads();
    }

    if (tid == 0) {
        float l[NEXP];
#pragma unroll
        for (int e = 0; e < NEXP; e++)
            l[e] = red[e][0] + bg[e] + NOISE_SCALE * noise[(size_t)n * NEXP + e];
        if (out_logits) {
#pragma unroll
            for (int e = 0; e < NEXP; e++)
                out_logits[(size_t)n * NEXP + e] = l[e];
        }
        int i0 = 0;
#pragma unroll
        for (int e = 1; e < NEXP; e++) if (l[e] > l[i0]) i0 = e;
        int i1 = (i0 == 0) ? 1 : 0;
#pragma unroll
        for (int e = 0; e < NEXP; e++) if (e != i0 && l[e] > l[i1]) i1 = e;

        float r = expf(l[i1] - l[i0]);
        float w0 = 1.0f / (1.0f + r);
        float w1 = r / (1.0f + r);
        g_sel[n * TOPK + 0] = i0;
        g_sel[n * TOPK + 1] = i1;
        g_wt [n * TOPK + 0] = w0;
        g_wt [n * TOPK + 1] = w1;
        if (out_sel) {
            out_sel[n * TOPK + 0] = (float)i0;
            out_sel[n * TOPK + 1] = (float)i1;
        }
    }
}

// ---------------- stable per-expert compaction -------------------------------
__global__ void build_lists_kernel() {
    int e = blockIdx.x;
    int lane = threadIdx.x;
    int c = 0;
    for (int n0 = 0; n0 < NTOK; n0 += 32) {
        int n = n0 + lane;
        int s0 = g_sel[n * TOPK + 0];
        int s1 = g_sel[n * TOPK + 1];
        bool m0 = (s0 == e), m1 = (s1 == e);
        bool any = m0 || m1;
        unsigned mask = __ballot_sync(0xffffffffu, any);
        if (any) {
            int pos = c + __popc(mask & ((1u << lane) - 1u));
            g_list[e * NTOK + pos] = n;
            g_lw  [e * NTOK + pos] = m0 ? g_wt[n * TOPK + 0] : g_wt[n * TOPK + 1];
        }
        c += __popc(mask);
    }
    if (lane == 0) g_cnt[e] = c;
}

// ---------------- GEMM1 (fp16 mma + ldmatrix): act = silu(X@W1+b1)*(X@W3+b3) -
// grid: (m=16, n=64, e=8), 256 threads, 3-stage cp.async (distance-2 prefetch)
__global__ __launch_bounds__(256, 1)
void gemm1_kernel(const float* __restrict__ b1, const float* __restrict__ b3) {
    int e   = blockIdx.z;
    int cnt = g_cnt[e];
    int m0  = blockIdx.x * BM;
    if (m0 >= cnt) return;
    int n0  = blockIdx.y * BN;

    extern __shared__ __align__(16) __half smem[];
    const int STG = ATILE + 2 * BTILE;    // halves per stage
    __shared__ int toks[BM];

    int tid = threadIdx.x;
    if (tid < BM) {
        int r = m0 + tid;
        toks[tid] = (r < cnt) ? g_list[e * NTOK + r] : -1;
    }
    __syncthreads();

    // staging: A 1024 chunks (4/thread), B1 512 (2/thread), B3 512 (2/thread)
    int arow = tid >> 1, apart = (tid & 1) * 4;       // 4 consecutive 16B parts
    int tokA = toks[arow]; if (tokA < 0) tokA = 0;
    int brow = tid >> 2, bpart = (tid & 3) * 2;       // 2 consecutive parts

    const __half* pA  = g_x16 + (size_t)tokA * HDIM + apart * 8;
    const __half* pB1 = g_w1t + ((size_t)e * FDIM + n0 + brow) * HDIM + bpart * 8;
    const __half* pB3 = g_w3t + ((size_t)e * FDIM + n0 + brow) * HDIM + bpart * 8;

    unsigned uS0 = (unsigned)__cvta_generic_to_shared(smem);
    unsigned uA  = uS0 + (unsigned)(arow * AS_STR + apart * 8) * 2;
    unsigned uB1 = uS0 + (unsigned)(ATILE + brow * AS_STR + bpart * 8) * 2;
    unsigned uB3 = uS0 + (unsigned)(ATILE + BTILE + brow * AS_STR + bpart * 8) * 2;

#define G1_ISSUE(s, kof)                                                         \
    do {                                                                         \
        unsigned sb_ = (unsigned)(s) * STG * 2;                                  \
        cpa16(uA  + sb_,      pA  + (kof));                                      \
        cpa16(uA  + sb_ + 16, pA  + (kof) + 8);                                  \
        cpa16(uA  + sb_ + 32, pA  + (kof) + 16);                                 \
        cpa16(uA  + sb_ + 48, pA  + (kof) + 24);                                 \
        cpa16(uB1 + sb_,      pB1 + (kof));                                      \
        cpa16(uB1 + sb_ + 16, pB1 + (kof) + 8);                                  \
        cpa16(uB3 + sb_,      pB3 + (kof));                                      \
        cpa16(uB3 + sb_ + 16, pB3 + (kof) + 8);                                  \
        CP_COMMIT();                                                             \
    } while (0)

    // preload stages 0,1 (iterations 0,1)
    G1_ISSUE(0, 0);
    G1_ISSUE(1, BK);

    int lane = tid & 31, warp = tid >> 5;
    int wm = warp & 3, wn = warp >> 2;      // 4 x 2 warps -> 32x32 each
    int mb = wm * 32, nb = wn * 32;
    int r = lane >> 2, q = lane & 3;

    // ldmatrix lane addressing (4 groups of 8 lanes)
    int lr = lane & 7, lg = lane >> 3;
    // A 16x16 tile: m0=(row,k0) m1=(row+8,k0) m2=(row,k8) m3=(row+8,k8)
    int a_row  = mb + lr + 8 * (lg & 1);
    int a_koff = 8 * (lg >> 1);
    // B 16x16 (two n-groups): m0=(n,k0) m1=(n,k8) m2=(n+8,k0) m3=(n+8,k8)
    int b_col  = nb + lr + 8 * (lg >> 1);
    int b_koff = 8 * (lg & 1);

    unsigned aoff0 = (unsigned)(a_row * AS_STR + a_koff) * 2;            // A region rel
    unsigned aoff1 = aoff0 + (unsigned)(16 * AS_STR) * 2;
    unsigned boff0 = (unsigned)(b_col * AS_STR + b_koff) * 2;            // B region rel
    unsigned boff1 = boff0 + (unsigned)(16 * AS_STR) * 2;
    const unsigned uB1rel = (unsigned)ATILE * 2;
    const unsigned uB3rel = (unsigned)(ATILE + BTILE) * 2;

    float acc1[2][4][4], acc3[2][4][4];
#pragma unroll
    for (int i = 0; i < 2; i++)
#pragma unroll
        for (int j = 0; j < 4; j++)
#pragma unroll
            for (int c = 0; c < 4; c++) { acc1[i][j][c] = 0.f; acc3[i][j][c] = 0.f; }

    const int NIT = HDIM / BK;   // 16
    for (int it = 0; it < NIT; it++) {
        if (it < NIT - 1) CP_WAIT1(); else CP_WAIT0();
        __syncthreads();
        // prefetch it+2 into stage (it+2)%3: last READ at it-1; sync above orders it.
        if (it + 2 < NIT) G1_ISSUE((it + 2) % NSTG, (it + 2) * BK);

        int st = it % NSTG;
        unsigned uStage = uS0 + (unsigned)(st * STG) * 2;

#pragma unroll
        for (int ks = 0; ks < 4; ks++) {
            unsigned kb = (unsigned)ks * 32u;
            unsigned af0[4], af1[4];
            LDSM4(af0[0], af0[1], af0[2], af0[3], uStage + aoff0 + kb);
            LDSM4(af1[0], af1[1], af1[2], af1[3], uStage + aoff1 + kb);
#pragma unroll
            for (int jj = 0; jj < 2; jj++) {
                unsigned bo = (jj == 0) ? boff0 : boff1;
                unsigned p0, p1, p2, p3;
                LDSM4(p0, p1, p2, p3, uStage + uB1rel + bo + kb);
                MMA_F16(acc1[0][2*jj],   af0[0], af0[1], af0[2], af0[3], p0, p1);
                MMA_F16(acc1[1][2*jj],   af1[0], af1[1], af1[2], af1[3], p0, p1);
                MMA_F16(acc1[0][2*jj+1], af0[0], af0[1], af0[2], af0[3], p2, p3);
                MMA_F16(acc1[1][2*jj+1], af1[0], af1[1], af1[2], af1[3], p2, p3);
                unsigned t0, t1, t2, t3;
                LDSM4(t0, t1, t2, t3, uStage + uB3rel + bo + kb);
                MMA_F16(acc3[0][2*jj],   af0[0], af0[1], af0[2], af0[3], t0, t1);
                MMA_F16(acc3[1][2*jj],   af1[0], af1[1], af1[2], af1[3], t0, t1);
                MMA_F16(acc3[0][2*jj+1], af0[0], af0[1], af0[2], af0[3], t2, t3);
                MMA_F16(acc3[1][2*jj+1], af1[0], af1[1], af1[2], af1[3], t2, t3);
            }
        }
    }
#undef G1_ISSUE

    // epilogue: silu(h)*g -> fp16 act
#pragma unroll
    for (int j = 0; j < 4; j++) {
        int col = n0 + nb + 8 * j + q * 2;
        float2 bv1 = *(const float2*)(b1 + (size_t)e * FDIM + col);
        float2 bv3 = *(const float2*)(b3 + (size_t)e * FDIM + col);
#pragma unroll
        for (int i = 0; i < 2; i++) {
#pragma unroll
            for (int h = 0; h < 2; h++) {
                int rl = mb + 16 * i + r + 8 * h;
                int rr = m0 + rl;
                if (rr < cnt) {
                    float v0 = siluf(acc1[i][j][2*h+0] + bv1.x) * (acc3[i][j][2*h+0] + bv3.x);
                    float v1 = siluf(acc1[i][j][2*h+1] + bv1.y) * (acc3[i][j][2*h+1] + bv3.y);
                    __half2 hv = __floats2half2_rn(v0, v1);
                    *(__half2*)(g_act + ((size_t)e * NTOK + rr) * FDIM + col) = hv;
                }
            }
        }
    }
}

// ---------------- GEMM2 (fp16 mma + ldmatrix): out[tok] += w * (act@W2 + b2) -
// grid: (m=16, n=16, e=8), 256 threads, 3-stage pipeline, 2 CTAs/SM
__global__ __launch_bounds__(256, 2)
void gemm2_kernel(const float* __restrict__ b2, float* __restrict__ out) {
    int e   = blockIdx.z;
    int cnt = g_cnt[e];
    int m0  = blockIdx.x * BM;
    if (m0 >= cnt) return;
    int n0  = blockIdx.y * BN;

    extern __shared__ __align__(16) __half smem[];
    const int STG = ATILE + BTILE;
    __shared__ int   toks[BM];
    __shared__ float ws[BM];

    int tid = threadIdx.x;
    if (tid < BM) {
        int rr = m0 + tid;
        toks[tid] = (rr < cnt) ? g_list[e * NTOK + rr] : -1;
        ws[tid]   = (rr < cnt) ? g_lw  [e * NTOK + rr] : 0.0f;
    }
    __syncthreads();

    int arow = tid >> 1, apart = (tid & 1) * 4;
    int ra = (m0 + arow < cnt) ? arow : 0;
    int brow = tid >> 2, bpart = (tid & 3) * 2;

    const __half* pA = g_act + ((size_t)e * NTOK + m0 + ra) * FDIM + apart * 8;
    const __half* pB = g_w2t + ((size_t)e * HDIM + n0 + brow) * FDIM + bpart * 8;

    unsigned uS0 = (unsigned)__cvta_generic_to_shared(smem);
    unsigned uA = uS0 + (unsigned)(arow * AS_STR + apart * 8) * 2;
    unsigned uB = uS0 + (unsigned)(ATILE + brow * AS_STR + bpart * 8) * 2;

#define G2_ISSUE(s, kof)                                                         \
    do {                                                                         \
        unsigned sb_ = (unsigned)(s) * STG * 2;                                  \
        cpa16(uA + sb_,      pA + (kof));                                        \
        cpa16(uA + sb_ + 16, pA + (kof) + 8);                                    \
        cpa16(uA + sb_ + 32, pA + (kof) + 16);                                   \
        cpa16(uA + sb_ + 48, pA + (kof) + 24);                                   \
        cpa16(uB + sb_,      pB + (kof));                                        \
        cpa16(uB + sb_ + 16, pB + (kof) + 8);                                    \
        CP_COMMIT();                                                             \
    } while (0)

    G2_ISSUE(0, 0);
    G2_ISSUE(1, BK);

    int lane = tid & 31, warp = tid >> 5;
    int wm = warp & 3, wn = warp >> 2;
    int mb = wm * 32, nb = wn * 32;
    int r = lane >> 2, q = lane & 3;

    int lr = lane & 7, lg = lane >> 3;
    int a_row  = mb + lr + 8 * (lg & 1);
    int a_koff = 8 * (lg >> 1);
    int b_col  = nb + lr + 8 * (lg >> 1);
    int b_koff = 8 * (lg & 1);

    unsigned aoff0 = (unsigned)(a_row * AS_STR + a_koff) * 2;
    unsigned aoff1 = aoff0 + (unsigned)(16 * AS_STR) * 2;
    unsigned boff0 = (unsigned)(b_col * AS_STR + b_koff) * 2;
    unsigned boff1 = boff0 + (unsigned)(16 * AS_STR) * 2;
    const unsigned uBrel = (unsigned)ATILE * 2;

    float acc[2][4][4];
#pragma unroll
    for (int i = 0; i < 2; i++)
#pragma unroll
        for (int j = 0; j < 4; j++)
#pragma unroll
            for (int c = 0; c < 4; c++) acc[i][j][c] = 0.f;

    const int NIT = FDIM / BK;   // 64
    for (int it = 0; it < NIT; it++) {
        if (it < NIT - 1) CP_WAIT1(); else CP_WAIT0();
        __syncthreads();
        if (it + 2 < NIT) G2_ISSUE((it + 2) % NSTG, (it + 2) * BK);

        int st = it % NSTG;
        unsigned uStage = uS0 + (unsigned)(st * STG) * 2;

#pragma unroll
        for (int ks = 0; ks < 4; ks++) {
            unsigned kb = (unsigned)ks * 32u;
            unsigned af0[4], af1[4];
            LDSM4(af0[0], af0[1], af0[2], af0[3], uStage + aoff0 + kb);
            LDSM4(af1[0], af1[1], af1[2], af1[3], uStage + aoff1 + kb);
#pragma unroll
            for (int jj = 0; jj < 2; jj++) {
                unsigned bo = (jj == 0) ? boff0 : boff1;
                unsigned p0, p1, p2, p3;
                LDSM4(p0, p1, p2, p3, uStage + uBrel + bo + kb);
                MMA_F16(acc[0][2*jj],   af0[0], af0[1], af0[2], af0[3], p0, p1);
                MMA_F16(acc[1][2*jj],   af1[0], af1[1], af1[2], af1[3], p0, p1);
                MMA_F16(acc[0][2*jj+1], af0[0], af0[1], af0[2], af0[3], p2, p3);
                MMA_F16(acc[1][2*jj+1], af1[0], af1[1], af1[2], af1[3], p2, p3);
            }
        }
    }
#undef G2_ISSUE

#pragma unroll
    for (int j = 0; j < 4; j++) {
        int col = n0 + nb + 8 * j + q * 2;
        float2 bv = *(const float2*)(b2 + (size_t)e * HDIM + col);
#pragma unroll
        for (int i = 0; i < 2; i++) {
#pragma unroll
            for (int h = 0; h < 2; h++) {
                int rl = mb + 16 * i + r + 8 * h;
                int rr = m0 + rl;
                if (rr < cnt) {
                    int tok = toks[rl];
                    float w = ws[rl];
                    float* op = out + (size_t)tok * HDIM + col;
                    atomicAdd(op + 0, w * (acc[i][j][2*h+0] + bv.x));
                    atomicAdd(op + 1, w * (acc[i][j][2*h+1] + bv.y));
                }
            }
        }
    }
}

// ---------------- launch -----------------------------------------------------
extern "C" void kernel_launch(void* const* d_in, const int* in_sizes, int n_in,
                              void* d_out, int out_size) {
    const float* x     = (const float*)d_in[0];
    const float* noise = (const float*)d_in[1];
    const float* Wg    = (const float*)d_in[2];
    const float* bg    = (const float*)d_in[3];
    const float* W1    = (const float*)d_in[4];
    const float* b1    = (const float*)d_in[5];
    const float* W2    = (const float*)d_in[6];
    const float* b2    = (const float*)d_in[7];
    const float* W3    = (const float*)d_in[8];
    const float* b3    = (const float*)d_in[9];

    float* out = (float*)d_out;
    const size_t HID = (size_t)NTOK * HDIM;
    const size_t LOG = (size_t)NTOK * NEXP;
    const size_t SEL = (size_t)NTOK * TOPK;

    float* out_logits = nullptr;
    float* out_sel    = nullptr;
    if ((size_t)out_size >= HID + LOG)       out_logits = out + HID;
    if ((size_t)out_size >= HID + LOG + SEL) out_sel    = out + HID + LOG;

    cudaMemsetAsync(out, 0, HID * sizeof(float));

    convert_x_kernel<<<(NTOK * HDIM / 4) / 256, 256>>>(x);

    {
        dim3 blk(32, 8);
        dim3 g(4096, 1, 3 * NEXP);   // (K/32)*(N/32)=4096 tiles per (mat, e)
        transpose_convert_all<<<g, blk>>>(W1, W3, W2);
    }

    router_kernel<<<NTOK, 128>>>(x, noise, Wg, bg, out_logits, out_sel);
    build_lists_kernel<<<NEXP, 32>>>();

    const int smem1 = NSTG * (ATILE + 2 * BTILE) * sizeof(__half);  // 110592
    const int smem2 = NSTG * (ATILE + BTILE) * sizeof(__half);      // 82944
    cudaFuncSetAttribute(gemm1_kernel, cudaFuncAttributeMaxDynamicSharedMemorySize, smem1);
    cudaFuncSetAttribute(gemm2_kernel, cudaFuncAttributeMaxDynamicSharedMemorySize, smem2);

    dim3 g1(NTOK / BM, FDIM / BN, NEXP);   // (16, 64, 8), M fastest
    gemm1_kernel<<<g1, 256, smem1>>>(b1, b3);

    dim3 g2(NTOK / BM, HDIM / BN, NEXP);   // (16, 16, 8)
    gemm2_kernel<<<g2, 256, smem2>>>(b2, out);
}

// round 11
// speedup vs baseline: 3.8805x; 1.0797x over previous
#include <cuda_runtime.h>
#include <cuda_fp16.h>
#include <math.h>
#include <stdint.h>

// Problem shape (fixed)
#define NTOK 2048      // B*T
#define HDIM 1024      // H
#define FDIM 4096      // F
#define NEXP 8         // E
#define TOPK 2
#define NOISE_SCALE 0.01f

// GEMM tiling
#define BM 128
#define BN 64
#define BK 64
#define AS_STR 72              // BK + 8 pad (fp16 elems); row stride 144 B (16-aligned)
#define ATILE (BM * AS_STR)    // 9216 elems
#define BTILE (BN * AS_STR)    // 4608 elems
#define NSTG 3                 // pipeline stages (prefetch distance 2)

// ---------------- device scratch (allocation-free) ---------------------------
__device__ int   g_sel[NTOK * TOPK];
__device__ float g_wt [NTOK * TOPK];
__device__ int   g_cnt[NEXP];
__device__ int   g_list[NEXP * NTOK];
__device__ float g_lw  [NEXP * NTOK];

// fp16 weights transposed to [E][N][K]; fp16 x and activations
__device__ __align__(16) __half g_w1t[(size_t)NEXP * FDIM * HDIM];
__device__ __align__(16) __half g_w3t[(size_t)NEXP * FDIM * HDIM];
__device__ __align__(16) __half g_w2t[(size_t)NEXP * HDIM * FDIM];
__device__ __align__(16) __half g_x16[(size_t)NTOK * HDIM];
__device__ __align__(16) __half g_act[(size_t)NEXP * NTOK * FDIM];

__device__ __forceinline__ float siluf(float v) { return v / (1.0f + expf(-v)); }

#define MMA_F16(d, a0,a1,a2,a3, b0,b1)                                           \
    asm volatile("mma.sync.aligned.m16n8k16.row.col.f32.f16.f16.f32 "            \
                 "{%0,%1,%2,%3},{%4,%5,%6,%7},{%8,%9},{%0,%1,%2,%3};\n"          \
                 : "+f"(d[0]), "+f"(d[1]), "+f"(d[2]), "+f"(d[3])                \
                 : "r"(a0), "r"(a1), "r"(a2), "r"(a3), "r"(b0), "r"(b1))

#define LDSM4(r0,r1,r2,r3, addr)                                                 \
    asm volatile("ldmatrix.sync.aligned.m8n8.x4.shared.b16 {%0,%1,%2,%3}, [%4];" \
                 : "=r"(r0), "=r"(r1), "=r"(r2), "=r"(r3) : "r"(addr))

__device__ __forceinline__ void cpa16(unsigned dst, const void* src) {
    asm volatile("cp.async.ca.shared.global [%0], [%1], 16;\n" :: "r"(dst), "l"(src));
}
#define CP_COMMIT() asm volatile("cp.async.commit_group;\n")
#define CP_WAIT0()  asm volatile("cp.async.wait_group 0;\n")
#define CP_WAIT1()  asm volatile("cp.async.wait_group 1;\n")

// ---------------- conversion: x fp32 -> fp16 ---------------------------------
__global__ void convert_x_kernel(const float* __restrict__ x) {
    int i = blockIdx.x * blockDim.x + threadIdx.x;   // one float4 per thread
    float4 v = reinterpret_cast<const float4*>(x)[i];
    __half2 h0 = __floats2half2_rn(v.x, v.y);
    __half2 h1 = __floats2half2_rn(v.z, v.w);
    uint2 o;
    o.x = *reinterpret_cast<unsigned*>(&h0);
    o.y = *reinterpret_cast<unsigned*>(&h1);
    reinterpret_cast<uint2*>(g_x16)[i] = o;
}

// ---------------- fused transpose+convert for W1, W3, W2 ---------------------
// W[e][K][N] f32 -> Wt[e][N][K] fp16; tile 64(k) x 32(n); 128B coalesced stores.
// z = mat*NEXP + e; grid.x = (K/64)*(N/32) = 2048 for all three shapes.
__global__ void transpose_convert_all(const float* __restrict__ W1,
                                      const float* __restrict__ W3,
                                      const float* __restrict__ W2) {
    __shared__ float tile[64][33];
    int z = blockIdx.z;
    int mat = z >> 3;          // 0:W1, 1:W3, 2:W2
    int e   = z & 7;
    const float* W;
    __half* Wt;
    int K, N;
    if (mat == 0)      { W = W1; Wt = g_w1t; K = HDIM; N = FDIM; }
    else if (mat == 1) { W = W3; Wt = g_w3t; K = HDIM; N = FDIM; }
    else               { W = W2; Wt = g_w2t; K = FDIM; N = HDIM; }

    int ntn = N >> 5;
    int n0 = (blockIdx.x % ntn) << 5;
    int k0 = (blockIdx.x / ntn) << 6;

    const float* We = W + (size_t)e * K * N;
    int tx = threadIdx.x, ty = threadIdx.y;   // 32 x 8
#pragma unroll
    for (int j = 0; j < 64; j += 8)
        tile[ty + j][tx] = We[(size_t)(k0 + ty + j) * N + n0 + tx];
    __syncthreads();
    size_t base = (size_t)e * K * N;
#pragma unroll
    for (int j = 0; j < 32; j += 8) {
        int n = ty + j;
        __half2 hv = __floats2half2_rn(tile[2 * tx][n], tile[2 * tx + 1][n]);
        *(__half2*)&Wt[base + (size_t)(n0 + n) * K + k0 + 2 * tx] = hv;
    }
}

// ---------------- router -----------------------------------------------------
__global__ void router_kernel(const float* __restrict__ x,
                              const float* __restrict__ noise,
                              const float* __restrict__ Wg,
                              const float* __restrict__ bg,
                              float* out_logits, float* out_sel) {
    int n = blockIdx.x;
    int tid = threadIdx.x;          // 128
    const float* xr = x + (size_t)n * HDIM;

    float acc[NEXP];
#pragma unroll
    for (int e = 0; e < NEXP; e++) acc[e] = 0.0f;
    for (int h = tid; h < HDIM; h += 128) {
        float xv = xr[h];
        const float* wr = Wg + (size_t)h * NEXP;
#pragma unroll
        for (int e = 0; e < NEXP; e++) acc[e] += xv * wr[e];
    }

    __shared__ float red[NEXP][128];
#pragma unroll
    for (int e = 0; e < NEXP; e++) red[e][tid] = acc[e];
    __syncthreads();
    for (int s = 64; s > 0; s >>= 1) {
        if (tid < s) {
#pragma unroll
            for (int e = 0; e < NEXP; e++) red[e][tid] += red[e][tid + s];
        }
        __syncthreads();
    }

    if (tid == 0) {
        float l[NEXP];
#pragma unroll
        for (int e = 0; e < NEXP; e++)
            l[e] = red[e][0] + bg[e] + NOISE_SCALE * noise[(size_t)n * NEXP + e];
        if (out_logits) {
#pragma unroll
            for (int e = 0; e < NEXP; e++)
                out_logits[(size_t)n * NEXP + e] = l[e];
        }
        int i0 = 0;
#pragma unroll
        for (int e = 1; e < NEXP; e++) if (l[e] > l[i0]) i0 = e;
        int i1 = (i0 == 0) ? 1 : 0;
#pragma unroll
        for (int e = 0; e < NEXP; e++) if (e != i0 && l[e] > l[i1]) i1 = e;

        float r = expf(l[i1] - l[i0]);
        float w0 = 1.0f / (1.0f + r);
        float w1 = r / (1.0f + r);
        g_sel[n * TOPK + 0] = i0;
        g_sel[n * TOPK + 1] = i1;
        g_wt [n * TOPK + 0] = w0;
        g_wt [n * TOPK + 1] = w1;
        if (out_sel) {
            out_sel[n * TOPK + 0] = (float)i0;
            out_sel[n * TOPK + 1] = (float)i1;
        }
    }
}

// ---------------- stable per-expert compaction (parallel) --------------------
// 1 block, 1024 threads = 32 warps: warp w -> expert (w&7), token-chunk (w>>3).
// Phase 1 counts matches per (expert, chunk) and caches ballot masks; phase 2
// computes chunk bases and writes. Chunk-major replay preserves token order.
#define BL_CHUNK (NTOK / 4)            // 512 tokens per chunk
#define BL_ITER  (BL_CHUNK / 32)       // 16 ballots per warp
__global__ void build_lists_kernel() {
    __shared__ int      cnt_sh[NEXP][4];
    __shared__ unsigned mk_any[32][BL_ITER];
    __shared__ unsigned mk_m0 [32][BL_ITER];

    int tid = threadIdx.x, lane = tid & 31, w = tid >> 5;
    int e = w & 7, c = w >> 3;
    int tok0 = c * BL_CHUNK;

    int cc = 0;
#pragma unroll
    for (int i = 0; i < BL_ITER; i++) {
        int n = tok0 + i * 32 + lane;
        int s0 = g_sel[n * TOPK + 0];
        int s1 = g_sel[n * TOPK + 1];
        bool m0 = (s0 == e), m1 = (s1 == e);
        unsigned ma = __ballot_sync(0xffffffffu, m0 || m1);
        unsigned mz = __ballot_sync(0xffffffffu, m0);
        if (lane == 0) { mk_any[w][i] = ma; mk_m0[w][i] = mz; }
        cc += __popc(ma);
    }
    if (lane == 0) cnt_sh[e][c] = cc;
    __syncthreads();

    int base = 0;
#pragma unroll
    for (int k = 0; k < 4; k++) {
        if (k < c) base += cnt_sh[e][k];
    }
    if (c == 3 && lane == 0) g_cnt[e] = base + cnt_sh[e][3];

    int run = base;
#pragma unroll
    for (int i = 0; i < BL_ITER; i++) {
        unsigned ma = mk_any[w][i];
        unsigned mz = mk_m0[w][i];
        int n = tok0 + i * 32 + lane;
        if (ma & (1u << lane)) {
            int pos = run + __popc(ma & ((1u << lane) - 1u));
            g_list[e * NTOK + pos] = n;
            bool is0 = (mz >> lane) & 1u;
            g_lw[e * NTOK + pos] = g_wt[n * TOPK + (is0 ? 0 : 1)];
        }
        run += __popc(ma);
    }
}

// ---------------- GEMM1 (fp16 mma + ldmatrix): act = silu(X@W1+b1)*(X@W3+b3) -
// grid: (m=16, n=64, e=8), 256 threads, 3-stage cp.async (distance-2 prefetch)
__global__ __launch_bounds__(256, 1)
void gemm1_kernel(const float* __restrict__ b1, const float* __restrict__ b3) {
    int e   = blockIdx.z;
    int cnt = g_cnt[e];
    int m0  = blockIdx.x * BM;
    if (m0 >= cnt) return;
    int n0  = blockIdx.y * BN;

    extern __shared__ __align__(16) __half smem[];
    const int STG = ATILE + 2 * BTILE;    // halves per stage
    __shared__ int toks[BM];

    int tid = threadIdx.x;
    if (tid < BM) {
        int r = m0 + tid;
        toks[tid] = (r < cnt) ? g_list[e * NTOK + r] : -1;
    }
    __syncthreads();

    // staging: A 1024 chunks (4/thread), B1 512 (2/thread), B3 512 (2/thread)
    int arow = tid >> 1, apart = (tid & 1) * 4;       // 4 consecutive 16B parts
    int tokA = toks[arow]; if (tokA < 0) tokA = 0;
    int brow = tid >> 2, bpart = (tid & 3) * 2;       // 2 consecutive parts

    const __half* pA  = g_x16 + (size_t)tokA * HDIM + apart * 8;
    const __half* pB1 = g_w1t + ((size_t)e * FDIM + n0 + brow) * HDIM + bpart * 8;
    const __half* pB3 = g_w3t + ((size_t)e * FDIM + n0 + brow) * HDIM + bpart * 8;

    unsigned uS0 = (unsigned)__cvta_generic_to_shared(smem);
    unsigned uA  = uS0 + (unsigned)(arow * AS_STR + apart * 8) * 2;
    unsigned uB1 = uS0 + (unsigned)(ATILE + brow * AS_STR + bpart * 8) * 2;
    unsigned uB3 = uS0 + (unsigned)(ATILE + BTILE + brow * AS_STR + bpart * 8) * 2;

#define G1_ISSUE(s, kof)                                                         \
    do {                                                                         \
        unsigned sb_ = (unsigned)(s) * STG * 2;                                  \
        cpa16(uA  + sb_,      pA  + (kof));                                      \
        cpa16(uA  + sb_ + 16, pA  + (kof) + 8);                                  \
        cpa16(uA  + sb_ + 32, pA  + (kof) + 16);                                 \
        cpa16(uA  + sb_ + 48, pA  + (kof) + 24);                                 \
        cpa16(uB1 + sb_,      pB1 + (kof));                                      \
        cpa16(uB1 + sb_ + 16, pB1 + (kof) + 8);                                  \
        cpa16(uB3 + sb_,      pB3 + (kof));                                      \
        cpa16(uB3 + sb_ + 16, pB3 + (kof) + 8);                                  \
        CP_COMMIT();                                                             \
    } while (0)

    // preload stages 0,1 (iterations 0,1)
    G1_ISSUE(0, 0);
    G1_ISSUE(1, BK);

    int lane = tid & 31, warp = tid >> 5;
    int wm = warp & 3, wn = warp >> 2;      // 4 x 2 warps -> 32x32 each
    int mb = wm * 32, nb = wn * 32;
    int r = lane >> 2, q = lane & 3;

    // ldmatrix lane addressing (4 groups of 8 lanes)
    int lr = lane & 7, lg = lane >> 3;
    int a_row  = mb + lr + 8 * (lg & 1);
    int a_koff = 8 * (lg >> 1);
    int b_col  = nb + lr + 8 * (lg >> 1);
    int b_koff = 8 * (lg & 1);

    unsigned aoff0 = (unsigned)(a_row * AS_STR + a_koff) * 2;            // A region rel
    unsigned aoff1 = aoff0 + (unsigned)(16 * AS_STR) * 2;
    unsigned boff0 = (unsigned)(b_col * AS_STR + b_koff) * 2;            // B region rel
    unsigned boff1 = boff0 + (unsigned)(16 * AS_STR) * 2;
    const unsigned uB1rel = (unsigned)ATILE * 2;
    const unsigned uB3rel = (unsigned)(ATILE + BTILE) * 2;

    float acc1[2][4][4], acc3[2][4][4];
#pragma unroll
    for (int i = 0; i < 2; i++)
#pragma unroll
        for (int j = 0; j < 4; j++)
#pragma unroll
            for (int c = 0; c < 4; c++) { acc1[i][j][c] = 0.f; acc3[i][j][c] = 0.f; }

    const int NIT = HDIM / BK;   // 16
    for (int it = 0; it < NIT; it++) {
        if (it < NIT - 1) CP_WAIT1(); else CP_WAIT0();
        __syncthreads();
        // prefetch it+2 into stage (it+2)%3: last READ at it-1; sync above orders it.
        if (it + 2 < NIT) G1_ISSUE((it + 2) % NSTG, (it + 2) * BK);

        int st = it % NSTG;
        unsigned uStage = uS0 + (unsigned)(st * STG) * 2;

#pragma unroll
        for (int ks = 0; ks < 4; ks++) {
            unsigned kb = (unsigned)ks * 32u;
            unsigned af0[4], af1[4];
            LDSM4(af0[0], af0[1], af0[2], af0[3], uStage + aoff0 + kb);
            LDSM4(af1[0], af1[1], af1[2], af1[3], uStage + aoff1 + kb);
#pragma unroll
            for (int jj = 0; jj < 2; jj++) {
                unsigned bo = (jj == 0) ? boff0 : boff1;
                unsigned p0, p1, p2, p3;
                LDSM4(p0, p1, p2, p3, uStage + uB1rel + bo + kb);
                MMA_F16(acc1[0][2*jj],   af0[0], af0[1], af0[2], af0[3], p0, p1);
                MMA_F16(acc1[1][2*jj],   af1[0], af1[1], af1[2], af1[3], p0, p1);
                MMA_F16(acc1[0][2*jj+1], af0[0], af0[1], af0[2], af0[3], p2, p3);
                MMA_F16(acc1[1][2*jj+1], af1[0], af1[1], af1[2], af1[3], p2, p3);
                unsigned t0, t1, t2, t3;
                LDSM4(t0, t1, t2, t3, uStage + uB3rel + bo + kb);
                MMA_F16(acc3[0][2*jj],   af0[0], af0[1], af0[2], af0[3], t0, t1);
                MMA_F16(acc3[1][2*jj],   af1[0], af1[1], af1[2], af1[3], t0, t1);
                MMA_F16(acc3[0][2*jj+1], af0[0], af0[1], af0[2], af0[3], t2, t3);
                MMA_F16(acc3[1][2*jj+1], af1[0], af1[1], af1[2], af1[3], t2, t3);
            }
        }
    }
#undef G1_ISSUE

    // epilogue: silu(h)*g -> fp16 act
#pragma unroll
    for (int j = 0; j < 4; j++) {
        int col = n0 + nb + 8 * j + q * 2;
        float2 bv1 = *(const float2*)(b1 + (size_t)e * FDIM + col);
        float2 bv3 = *(const float2*)(b3 + (size_t)e * FDIM + col);
#pragma unroll
        for (int i = 0; i < 2; i++) {
#pragma unroll
            for (int h = 0; h < 2; h++) {
                int rl = mb + 16 * i + r + 8 * h;
                int rr = m0 + rl;
                if (rr < cnt) {
                    float v0 = siluf(acc1[i][j][2*h+0] + bv1.x) * (acc3[i][j][2*h+0] + bv3.x);
                    float v1 = siluf(acc1[i][j][2*h+1] + bv1.y) * (acc3[i][j][2*h+1] + bv3.y);
                    __half2 hv = __floats2half2_rn(v0, v1);
                    *(__half2*)(g_act + ((size_t)e * NTOK + rr) * FDIM + col) = hv;
                }
            }
        }
    }
}

// ---------------- GEMM2 (fp16 mma + ldmatrix): out[tok] += w * (act@W2 + b2) -
// grid: (m=16, n=16, e=8), 256 threads, 3-stage pipeline, 2 CTAs/SM
__global__ __launch_bounds__(256, 2)
void gemm2_kernel(const float* __restrict__ b2, float* __restrict__ out) {
    int e   = blockIdx.z;
    int cnt = g_cnt[e];
    int m0  = blockIdx.x * BM;
    if (m0 >= cnt) return;
    int n0  = blockIdx.y * BN;

    extern __shared__ __align__(16) __half smem[];
    const int STG = ATILE + BTILE;
    __shared__ int   toks[BM];
    __shared__ float ws[BM];

    int tid = threadIdx.x;
    if (tid < BM) {
        int rr = m0 + tid;
        toks[tid] = (rr < cnt) ? g_list[e * NTOK + rr] : -1;
        ws[tid]   = (rr < cnt) ? g_lw  [e * NTOK + rr] : 0.0f;
    }
    __syncthreads();

    int arow = tid >> 1, apart = (tid & 1) * 4;
    int ra = (m0 + arow < cnt) ? arow : 0;
    int brow = tid >> 2, bpart = (tid & 3) * 2;

    const __half* pA = g_act + ((size_t)e * NTOK + m0 + ra) * FDIM + apart * 8;
    const __half* pB = g_w2t + ((size_t)e * HDIM + n0 + brow) * FDIM + bpart * 8;

    unsigned uS0 = (unsigned)__cvta_generic_to_shared(smem);
    unsigned uA = uS0 + (unsigned)(arow * AS_STR + apart * 8) * 2;
    unsigned uB = uS0 + (unsigned)(ATILE + brow * AS_STR + bpart * 8) * 2;

#define G2_ISSUE(s, kof)                                                         \
    do {                                                                         \
        unsigned sb_ = (unsigned)(s) * STG * 2;                                  \
        cpa16(uA + sb_,      pA + (kof));                                        \
        cpa16(uA + sb_ + 16, pA + (kof) + 8);                                    \
        cpa16(uA + sb_ + 32, pA + (kof) + 16);                                   \
        cpa16(uA + sb_ + 48, pA + (kof) + 24);                                   \
        cpa16(uB + sb_,      pB + (kof));                                        \
        cpa16(uB + sb_ + 16, pB + (kof) + 8);                                    \
        CP_COMMIT();                                                             \
    } while (0)

    G2_ISSUE(0, 0);
    G2_ISSUE(1, BK);

    int lane = tid & 31, warp = tid >> 5;
    int wm = warp & 3, wn = warp >> 2;
    int mb = wm * 32, nb = wn * 32;
    int r = lane >> 2, q = lane & 3;

    int lr = lane & 7, lg = lane >> 3;
    int a_row  = mb + lr + 8 * (lg & 1);
    int a_koff = 8 * (lg >> 1);
    int b_col  = nb + lr + 8 * (lg >> 1);
    int b_koff = 8 * (lg & 1);

    unsigned aoff0 = (unsigned)(a_row * AS_STR + a_koff) * 2;
    unsigned aoff1 = aoff0 + (unsigned)(16 * AS_STR) * 2;
    unsigned boff0 = (unsigned)(b_col * AS_STR + b_koff) * 2;
    unsigned boff1 = boff0 + (unsigned)(16 * AS_STR) * 2;
    const unsigned uBrel = (unsigned)ATILE * 2;

    float acc[2][4][4];
#pragma unroll
    for (int i = 0; i < 2; i++)
#pragma unroll
        for (int j = 0; j < 4; j++)
#pragma unroll
            for (int c = 0; c < 4; c++) acc[i][j][c] = 0.f;

    const int NIT = FDIM / BK;   // 64
    for (int it = 0; it < NIT; it++) {
        if (it < NIT - 1) CP_WAIT1(); else CP_WAIT0();
        __syncthreads();
        if (it + 2 < NIT) G2_ISSUE((it + 2) % NSTG, (it + 2) * BK);

        int st = it % NSTG;
        unsigned uStage = uS0 + (unsigned)(st * STG) * 2;

#pragma unroll
        for (int ks = 0; ks < 4; ks++) {
            unsigned kb = (unsigned)ks * 32u;
            unsigned af0[4], af1[4];
            LDSM4(af0[0], af0[1], af0[2], af0[3], uStage + aoff0 + kb);
            LDSM4(af1[0], af1[1], af1[2], af1[3], uStage + aoff1 + kb);
#pragma unroll
            for (int jj = 0; jj < 2; jj++) {
                unsigned bo = (jj == 0) ? boff0 : boff1;
                unsigned p0, p1, p2, p3;
                LDSM4(p0, p1, p2, p3, uStage + uBrel + bo + kb);
                MMA_F16(acc[0][2*jj],   af0[0], af0[1], af0[2], af0[3], p0, p1);
                MMA_F16(acc[1][2*jj],   af1[0], af1[1], af1[2], af1[3], p0, p1);
                MMA_F16(acc[0][2*jj+1], af0[0], af0[1], af0[2], af0[3], p2, p3);
                MMA_F16(acc[1][2*jj+1], af1[0], af1[1], af1[2], af1[3], p2, p3);
            }
        }
    }
#undef G2_ISSUE

#pragma unroll
    for (int j = 0; j < 4; j++) {
        int col = n0 + nb + 8 * j + q * 2;
        float2 bv = *(const float2*)(b2 + (size_t)e * HDIM + col);
#pragma unroll
        for (int i = 0; i < 2; i++) {
#pragma unroll
            for (int h = 0; h < 2; h++) {
                int rl = mb + 16 * i + r + 8 * h;
                int rr = m0 + rl;
                if (rr < cnt) {
                    int tok = toks[rl];
                    float w = ws[rl];
                    float* op = out + (size_t)tok * HDIM + col;
                    atomicAdd(op + 0, w * (acc[i][j][2*h+0] + bv.x));
                    atomicAdd(op + 1, w * (acc[i][j][2*h+1] + bv.y));
                }
            }
        }
    }
}

// ---------------- launch -----------------------------------------------------
extern "C" void kernel_launch(void* const* d_in, const int* in_sizes, int n_in,
                              void* d_out, int out_size) {
    const float* x     = (const float*)d_in[0];
    const float* noise = (const float*)d_in[1];
    const float* Wg    = (const float*)d_in[2];
    const float* bg    = (const float*)d_in[3];
    const float* W1    = (const float*)d_in[4];
    const float* b1    = (const float*)d_in[5];
    const float* W2    = (const float*)d_in[6];
    const float* b2    = (const float*)d_in[7];
    const float* W3    = (const float*)d_in[8];
    const float* b3    = (const float*)d_in[9];

    float* out = (float*)d_out;
    const size_t HID = (size_t)NTOK * HDIM;
    const size_t LOG = (size_t)NTOK * NEXP;
    const size_t SEL = (size_t)NTOK * TOPK;

    float* out_logits = nullptr;
    float* out_sel    = nullptr;
    if ((size_t)out_size >= HID + LOG)       out_logits = out + HID;
    if ((size_t)out_size >= HID + LOG + SEL) out_sel    = out + HID + LOG;

    // order: small/latency kernels first, then weight transpose, then GEMMs
    convert_x_kernel<<<(NTOK * HDIM / 4) / 256, 256>>>(x);
    router_kernel<<<NTOK, 128>>>(x, noise, Wg, bg, out_logits, out_sel);
    build_lists_kernel<<<1, 1024>>>();

    {
        dim3 blk(32, 8);
        dim3 g(2048, 1, 3 * NEXP);   // (K/64)*(N/32)=2048 tiles per (mat, e)
        transpose_convert_all<<<g, blk>>>(W1, W3, W2);
    }

    cudaMemsetAsync(out, 0, HID * sizeof(float));

    const int smem1 = NSTG * (ATILE + 2 * BTILE) * sizeof(__half);  // 110592
    const int smem2 = NSTG * (ATILE + BTILE) * sizeof(__half);      // 82944
    cudaFuncSetAttribute(gemm1_kernel, cudaFuncAttributeMaxDynamicSharedMemorySize, smem1);
    cudaFuncSetAttribute(gemm2_kernel, cudaFuncAttributeMaxDynamicSharedMemorySize, smem2);

    dim3 g1(NTOK / BM, FDIM / BN, NEXP);   // (16, 64, 8), M fastest
    gemm1_kernel<<<g1, 256, smem1>>>(b1, b3);

    dim3 g2(NTOK / BM, HDIM / BN, NEXP);   // (16, 16, 8)
    gemm2_kernel<<<g2, 256, smem2>>>(b2, out);
}